// round 11
// baseline (speedup 1.0000x reference)
#include <cuda_runtime.h>
#include <math.h>

#define FULLMASK 0xffffffffu
#define KSEL   9
#define SEGS   4
#define CHUNK  1792
#define CAP    16
#define GATE2  0.0036f      /* (0.06)^2 — keeps true top-9 w.p. ~1-1e-14; fallback covers the rest */
#define WARPS  8
#define TPB    256

#define INFKEY ((0x7f800000ULL << 32) | 0x7fffffffULL)

// ---------------- scratch (device globals; no allocation allowed) ----------
__device__ float g_part_focal[4096];
__device__ float g_part_bbox [4096];
__device__ float g_part_giou [4096];
__device__ float g_part_delta[4096];
__device__ int   g_ctr = 0;           // self-resetting completion counter

// ---------------- focal pieces ---------------------------------------------
__device__ __forceinline__ float focal_t0(float x) {
    float ax   = fabsf(x);
    float u    = __expf(-ax);
    float r    = __fdividef(1.0f, 1.0f + u);
    float prob = (x >= 0.0f) ? r : (1.0f - r);
    float sp   = fmaxf(x, 0.0f) + __logf(1.0f + u);
    return 0.75f * sp * (prob * prob);
}
__device__ __forceinline__ float focal_t1(float x) {
    float ax   = fabsf(x);
    float u    = __expf(-ax);
    float r    = __fdividef(1.0f, 1.0f + u);
    float prob = (x >= 0.0f) ? r : (1.0f - r);
    float q    = 1.0f - prob;
    float spn  = fmaxf(-x, 0.0f) + __logf(1.0f + u);
    return 0.25f * spn * (q * q);
}

// ---------------- top-9 helpers ---------------------------------------------
__device__ __forceinline__ void insert9(float (&dk)[KSEL], int (&ik)[KSEL],
                                        float d, int idx) {
    if (d < dk[KSEL - 1]) {
        dk[KSEL - 1] = d; ik[KSEL - 1] = idx;
#pragma unroll
        for (int j = KSEL - 1; j > 0; --j) {
            if (dk[j] < dk[j - 1]) {
                float td = dk[j]; dk[j] = dk[j - 1]; dk[j - 1] = td;
                int   ti = ik[j]; ik[j] = ik[j - 1]; ik[j - 1] = ti;
            }
        }
    }
}

// warp-merge per-lane sorted lists; lane r (r<9) returns the r-th best key.
__device__ __forceinline__ unsigned long long
warp_merge9(float (&dk)[KSEL], int (&ik)[KSEL], int lane) {
    unsigned long long mykey = INFKEY;
    unsigned long long key =
        (((unsigned long long)__float_as_uint(dk[0])) << 32) | (unsigned)ik[0];
#pragma unroll
    for (int r = 0; r < KSEL; ++r) {
        unsigned long long k = key;
#pragma unroll
        for (int off = 16; off > 0; off >>= 1) {
            unsigned long long o = __shfl_xor_sync(FULLMASK, k, off);
            k = (o < k) ? o : k;
        }
        if (lane == r) mykey = k;
        if (key == k) {
#pragma unroll
            for (int j = 0; j < KSEL - 1; ++j) { dk[j] = dk[j + 1]; ik[j] = ik[j + 1]; }
            dk[KSEL - 1] = __int_as_float(0x7f800000);
            ik[KSEL - 1] = 0x7fffffff;
            key = (((unsigned long long)__float_as_uint(dk[0])) << 32) | (unsigned)ik[0];
        }
    }
    return mykey;
}

// ---------------- the single fused kernel ------------------------------------
__global__ void __launch_bounds__(TPB, 4)
fused_kernel(const float*  __restrict__ logits,
             const float4* __restrict__ pred_boxes,
             const float2* __restrict__ locs,
             const float4* __restrict__ gt_boxes,
             const int*    __restrict__ gt_labels,
             float* __restrict__ out,
             int B, int N, int C, int G, int pairBlocks,
             int n4, int total,
             double invBNC, double invBB, double invGI)
{
    __shared__ __align__(16) union {
        struct {
            float2 sloc[CHUNK];                              // 14336 B
            unsigned long long sstk[WARPS][CAP][32];         // 32768 B
        } f;
        float  red[TPB];
        double dred[3][TPB];
    } sm;
    __shared__ int sticket;

    const int tid  = threadIdx.x;
    const int lane = tid & 31;
    const int warp = tid >> 5;
    const int bid  = blockIdx.x;
    const int grid = gridDim.x;
    const int P    = B * G;

    // ================= phase 1 (first pairBlocks blocks): pair work ==========
    if (bid < pairBlocks) {
        const int pair   = bid * WARPS + warp;
        const bool active = pair < P;
        float cx = 0.0f, cy = 0.0f;
        float4 gb = make_float4(0.f, 0.f, 0.f, 0.f);
        if (active) { gb = gt_boxes[pair]; cx = gb.x; cy = gb.y; }

        float dk[KSEL]; int ik[KSEL];
#pragma unroll
        for (int j = 0; j < KSEL; ++j) { dk[j] = __int_as_float(0x7f800000); ik[j] = 0x7fffffff; }
        bool ovf = false;

        const int segLen = (N + SEGS - 1) / SEGS;
        for (int seg = 0; seg < SEGS; ++seg) {
            const int s0 = seg * segLen;
            const int s1 = min(N, s0 + segLen);
            int cnt = 0;
            for (int base = s0; base < s1; base += CHUNK) {
                int c = min(CHUNK, s1 - base);
                __syncthreads();
                for (int i = tid; i < c; i += TPB) sm.f.sloc[i] = locs[base + i];
                __syncthreads();
                if (active) {
                    const float4* sl4 = (const float4*)sm.f.sloc;
                    int c2 = c >> 1;
                    for (int j = lane; j < c2; j += 32) {
                        float4 v  = sl4[j];
                        float dx0 = cx - v.x, dy0 = cy - v.y;
                        float dx1 = cx - v.z, dy1 = cy - v.w;
                        float d0  = fmaf(dx0, dx0, dy0 * dy0);
                        float d1  = fmaf(dx1, dx1, dy1 * dy1);
                        int   i0  = base + 2 * j;
                        if (d0 <= GATE2) {
                            if (cnt < CAP)
                                sm.f.sstk[warp][cnt][lane] =
                                    (((unsigned long long)__float_as_uint(d0)) << 32) | (unsigned)i0;
                            cnt++;
                        }
                        if (d1 <= GATE2) {
                            if (cnt < CAP)
                                sm.f.sstk[warp][cnt][lane] =
                                    (((unsigned long long)__float_as_uint(d1)) << 32) | (unsigned)(i0 + 1);
                            cnt++;
                        }
                    }
                    if ((c & 1) != 0) {
                        int i = base + c - 1;
                        if (lane == (i & 31)) {
                            float2 L = sm.f.sloc[c - 1];
                            float dx = cx - L.x, dy = cy - L.y;
                            float d  = fmaf(dx, dx, dy * dy);
                            if (d <= GATE2) {
                                if (cnt < CAP)
                                    sm.f.sstk[warp][cnt][lane] =
                                        (((unsigned long long)__float_as_uint(d)) << 32) | (unsigned)i;
                                cnt++;
                            }
                        }
                    }
                }
            }
            if (active) {
                int m = min(cnt, CAP);
                for (int i = 0; i < m; ++i) {
                    unsigned long long k = sm.f.sstk[warp][i][lane];
                    insert9(dk, ik, __uint_as_float((unsigned)(k >> 32)),
                            (int)(k & 0xffffffffULL));
                }
                ovf |= (cnt > CAP);
            }
        }

        unsigned long long mykey = INFKEY;
        if (active) {
            mykey = warp_merge9(dk, ik, lane);
            // safety: overflow or <9 survivors -> exact brute force (very rare)
            bool bad = (lane < KSEL) && ((unsigned)(mykey >> 32) >= 0x7f800000u);
            if (__ballot_sync(FULLMASK, ovf) || __ballot_sync(FULLMASK, bad)) {
#pragma unroll
                for (int j = 0; j < KSEL; ++j) { dk[j] = __int_as_float(0x7f800000); ik[j] = 0x7fffffff; }
                for (int n = lane; n < N; n += 32) {
                    float2 L = locs[n];
                    float dx = cx - L.x, dy = cy - L.y;
                    insert9(dk, ik, fmaf(dx, dx, dy * dy), n);
                }
                mykey = warp_merge9(dk, ik, lane);
            }

            // box losses + focal corrections for the 9 selected locations
            const int b = pair / G;
            float l1 = 0.0f, gl = 0.0f, delta = 0.0f;
            if (lane < KSEL) {
                int myN = (int)(mykey & 0xffffffffULL);
                float4 pb = pred_boxes[(long long)b * N + myN];
                l1 = fabsf(pb.x - gb.x) + fabsf(pb.y - gb.y)
                   + fabsf(pb.z - gb.z) + fabsf(pb.w - gb.w);

                float ax0 = pb.x - 0.5f * pb.z, ay0 = pb.y - 0.5f * pb.w;
                float ax1 = pb.x + 0.5f * pb.z, ay1 = pb.y + 0.5f * pb.w;
                float bx0 = gb.x - 0.5f * gb.z, by0 = gb.y - 0.5f * gb.w;
                float bx1 = gb.x + 0.5f * gb.z, by1 = gb.y + 0.5f * gb.w;

                float area_a = (ax1 - ax0) * (ay1 - ay0);
                float area_b = (bx1 - bx0) * (by1 - by0);
                float iw = fmaxf(fminf(ax1, bx1) - fmaxf(ax0, bx0), 0.0f);
                float ih = fmaxf(fminf(ay1, by1) - fmaxf(ay0, by0), 0.0f);
                float inter = iw * ih;
                float uni   = area_a + area_b - inter;
                float iou   = inter / uni;
                float cw = fmaxf(fmaxf(ax1, bx1) - fminf(ax0, bx0), 0.0f);
                float ch = fmaxf(fmaxf(ay1, by1) - fminf(ay0, by0), 0.0f);
                float areac = cw * ch;
                gl = 1.0f - (iou - (areac - uni) / areac);

                int lbl = gt_labels[pair];
                float x = logits[(long long)(b * N + myN) * C + lbl];
                delta = focal_t1(x) - focal_t0(x);
            }
#pragma unroll
            for (int off = 16; off > 0; off >>= 1) {
                l1    += __shfl_down_sync(FULLMASK, l1,    off);
                gl    += __shfl_down_sync(FULLMASK, gl,    off);
                delta += __shfl_down_sync(FULLMASK, delta, off);
            }
            if (lane == 0) {
                g_part_bbox [pair] = l1;
                g_part_giou [pair] = gl;
                g_part_delta[pair] = delta;
            }
        }
    }

    // ================= phase 2 (all blocks): uniform focal share ==============
    {
        const int per = (n4 + grid - 1) / grid;
        const int s   = bid * per;
        const int e   = min(n4, s + per);
        float acc = 0.0f;
        const float4* __restrict__ l4 = (const float4*)logits;
        for (int i = s + tid; i < e; i += TPB) {
            float4 v = l4[i];
            acc += focal_t0(v.x);
            acc += focal_t0(v.y);
            acc += focal_t0(v.z);
            acc += focal_t0(v.w);
        }
        if (bid == 0 && tid == 0) {
            for (int i = n4 * 4; i < total; ++i) acc += focal_t0(logits[i]);
        }
        __syncthreads();                  // smem union: done with pair data
        sm.red[tid] = acc;
        __syncthreads();
#pragma unroll
        for (int st = 128; st > 0; st >>= 1) {
            if (tid < st) sm.red[tid] += sm.red[tid + st];
            __syncthreads();
        }
        if (tid == 0) g_part_focal[bid] = sm.red[0];
    }

    // ================= phase 3: last block finalizes ==========================
    __threadfence();
    if (tid == 0) sticket = atomicAdd(&g_ctr, 1);
    __syncthreads();
    if (sticket == grid - 1) {
        double a0 = 0.0, a1 = 0.0, a2 = 0.0;
        for (int i = tid; i < grid; i += TPB) a0 += (double)g_part_focal[i];
        for (int i = tid; i < P; i += TPB) {
            a0 += (double)g_part_delta[i];
            a1 += (double)g_part_bbox [i];
            a2 += (double)g_part_giou [i];
        }
        sm.dred[0][tid] = a0;
        sm.dred[1][tid] = a1;
        sm.dred[2][tid] = a2;
        __syncthreads();
#pragma unroll
        for (int st = 128; st > 0; st >>= 1) {
            if (tid < st) {
                sm.dred[0][tid] += sm.dred[0][tid + st];
                sm.dred[1][tid] += sm.dred[1][tid + st];
                sm.dred[2][tid] += sm.dred[2][tid + st];
            }
            __syncthreads();
        }
        if (tid == 0) {
            out[0] = (float)(sm.dred[0][0] * invBNC);
            out[1] = (float)(sm.dred[1][0] * invBB);
            out[2] = (float)(sm.dred[2][0] * invGI);
            g_ctr  = 0;                   // self-reset for next graph replay
        }
    }
}

// ---------------- launch ----------------------------------------------------
extern "C" void kernel_launch(void* const* d_in, const int* in_sizes, int n_in,
                              void* d_out, int out_size)
{
    const float* logits = (const float*)d_in[0];   // (B,N,C)
    const float* pboxes = (const float*)d_in[1];   // (B,N,4)
    const float* locs   = (const float*)d_in[2];   // (N,2)
    const float* gboxes = (const float*)d_in[3];   // (B,G,4)
    const int*   glabel = (const int*)  d_in[4];   // (B,G)

    const int N = in_sizes[2] / 2;
    const int B = in_sizes[1] / (4 * N);
    const int C = in_sizes[0] / (B * N);
    const int G = in_sizes[4] / B;
    const int P = B * G;

    const int total = in_sizes[0];
    const int n4    = total / 4;

    int pairBlocks = (P + WARPS - 1) / WARPS;     // 128
    int grid = 4 * 148;                           // 4 CTAs/SM, full chip
    if (grid < pairBlocks) grid = pairBlocks;
    if (grid > 4096) grid = 4096;                 // g_part_focal capacity

    double invBNC = 1.0 / ((double)B * (double)N * (double)C);
    double invBB  = 1.0 / ((double)P * (double)KSEL * 4.0);
    double invGI  = 1.0 / ((double)P * (double)KSEL);

    fused_kernel<<<grid, TPB>>>(logits, (const float4*)pboxes,
                                (const float2*)locs, (const float4*)gboxes,
                                glabel, (float*)d_out,
                                B, N, C, G, pairBlocks,
                                n4, total, invBNC, invBB, invGI);
}

// round 12
// speedup vs baseline: 1.0721x; 1.0721x over previous
#include <cuda_runtime.h>
#include <math.h>

#define FULLMASK 0xffffffffu
#define KSEL   9
#define SEGS   4
#define CHUNK  1792
#define CAP    16
#define GATE2  0.0036f      /* (0.06)^2 — keeps true top-9 w.p. ~1-1e-14; fallback covers the rest */
#define WARPS  8
#define TPB    256

#define INFKEY ((0x7f800000ULL << 32) | 0x7fffffffULL)

// ---------------- scratch (device globals; no allocation allowed) ----------
__device__ float g_part_focal[4096];
__device__ float g_part_bbox [4096];
__device__ float g_part_giou [4096];
__device__ float g_part_delta[4096];
__device__ int   g_ctr = 0;           // self-resetting completion counter

// ---------------- focal pieces ---------------------------------------------
__device__ __forceinline__ float focal_t0(float x) {
    float ax   = fabsf(x);
    float u    = __expf(-ax);
    float r    = __fdividef(1.0f, 1.0f + u);
    float prob = (x >= 0.0f) ? r : (1.0f - r);
    float sp   = fmaxf(x, 0.0f) + __logf(1.0f + u);
    return 0.75f * sp * (prob * prob);
}
__device__ __forceinline__ float focal_t1(float x) {
    float ax   = fabsf(x);
    float u    = __expf(-ax);
    float r    = __fdividef(1.0f, 1.0f + u);
    float prob = (x >= 0.0f) ? r : (1.0f - r);
    float q    = 1.0f - prob;
    float spn  = fmaxf(-x, 0.0f) + __logf(1.0f + u);
    return 0.25f * spn * (q * q);
}

// ---------------- top-9 helpers ---------------------------------------------
__device__ __forceinline__ void insert9(float (&dk)[KSEL], int (&ik)[KSEL],
                                        float d, int idx) {
    if (d < dk[KSEL - 1]) {
        dk[KSEL - 1] = d; ik[KSEL - 1] = idx;
#pragma unroll
        for (int j = KSEL - 1; j > 0; --j) {
            if (dk[j] < dk[j - 1]) {
                float td = dk[j]; dk[j] = dk[j - 1]; dk[j - 1] = td;
                int   ti = ik[j]; ik[j] = ik[j - 1]; ik[j - 1] = ti;
            }
        }
    }
}

// warp-merge per-lane sorted lists; lane r (r<9) returns the r-th best key.
__device__ __forceinline__ unsigned long long
warp_merge9(float (&dk)[KSEL], int (&ik)[KSEL], int lane) {
    unsigned long long mykey = INFKEY;
    unsigned long long key =
        (((unsigned long long)__float_as_uint(dk[0])) << 32) | (unsigned)ik[0];
#pragma unroll
    for (int r = 0; r < KSEL; ++r) {
        unsigned long long k = key;
#pragma unroll
        for (int off = 16; off > 0; off >>= 1) {
            unsigned long long o = __shfl_xor_sync(FULLMASK, k, off);
            k = (o < k) ? o : k;
        }
        if (lane == r) mykey = k;
        if (key == k) {
#pragma unroll
            for (int j = 0; j < KSEL - 1; ++j) { dk[j] = dk[j + 1]; ik[j] = ik[j + 1]; }
            dk[KSEL - 1] = __int_as_float(0x7f800000);
            ik[KSEL - 1] = 0x7fffffff;
            key = (((unsigned long long)__float_as_uint(dk[0])) << 32) | (unsigned)ik[0];
        }
    }
    return mykey;
}

// ---------------- the single fused kernel ------------------------------------
__global__ void __launch_bounds__(TPB, 4)
fused_kernel(const float*  __restrict__ logits,
             const float4* __restrict__ pred_boxes,
             const float2* __restrict__ locs,
             const float4* __restrict__ gt_boxes,
             const int*    __restrict__ gt_labels,
             float* __restrict__ out,
             int B, int N, int C, int G, int pairBlocks,
             int n4, int total,
             double invBNC, double invBB, double invGI)
{
    __shared__ __align__(16) union {
        struct {
            float2 sloc[CHUNK];                              // 14336 B
            unsigned long long sstk[WARPS][CAP][32];         // 32768 B
        } f;
        float  red[TPB];
        double dred[3][TPB];
    } sm;
    __shared__ int sticket;

    const int tid  = threadIdx.x;
    const int lane = tid & 31;
    const int warp = tid >> 5;
    const int bid  = blockIdx.x;
    const int grid = gridDim.x;
    const int P    = B * G;

    // ================= phase 1 (first pairBlocks blocks): pair work ==========
    if (bid < pairBlocks) {
        const int pair   = bid * WARPS + warp;
        const bool active = pair < P;
        float cx = 0.0f, cy = 0.0f;
        float4 gb = make_float4(0.f, 0.f, 0.f, 0.f);
        if (active) { gb = gt_boxes[pair]; cx = gb.x; cy = gb.y; }

        float dk[KSEL]; int ik[KSEL];
#pragma unroll
        for (int j = 0; j < KSEL; ++j) { dk[j] = __int_as_float(0x7f800000); ik[j] = 0x7fffffff; }
        bool ovf = false;

        const int segLen = (N + SEGS - 1) / SEGS;
        for (int seg = 0; seg < SEGS; ++seg) {
            const int s0 = seg * segLen;
            const int s1 = min(N, s0 + segLen);
            int cnt = 0;
            for (int base = s0; base < s1; base += CHUNK) {
                int c = min(CHUNK, s1 - base);
                __syncthreads();
                for (int i = tid; i < c; i += TPB) sm.f.sloc[i] = locs[base + i];
                __syncthreads();
                if (active) {
                    const float4* sl4 = (const float4*)sm.f.sloc;
                    int c2 = c >> 1;
                    for (int j = lane; j < c2; j += 32) {
                        float4 v  = sl4[j];
                        float dx0 = cx - v.x, dy0 = cy - v.y;
                        float dx1 = cx - v.z, dy1 = cy - v.w;
                        float d0  = fmaf(dx0, dx0, dy0 * dy0);
                        float d1  = fmaf(dx1, dx1, dy1 * dy1);
                        int   i0  = base + 2 * j;
                        if (d0 <= GATE2) {
                            if (cnt < CAP)
                                sm.f.sstk[warp][cnt][lane] =
                                    (((unsigned long long)__float_as_uint(d0)) << 32) | (unsigned)i0;
                            cnt++;
                        }
                        if (d1 <= GATE2) {
                            if (cnt < CAP)
                                sm.f.sstk[warp][cnt][lane] =
                                    (((unsigned long long)__float_as_uint(d1)) << 32) | (unsigned)(i0 + 1);
                            cnt++;
                        }
                    }
                    if ((c & 1) != 0) {
                        int i = base + c - 1;
                        if (lane == (i & 31)) {
                            float2 L = sm.f.sloc[c - 1];
                            float dx = cx - L.x, dy = cy - L.y;
                            float d  = fmaf(dx, dx, dy * dy);
                            if (d <= GATE2) {
                                if (cnt < CAP)
                                    sm.f.sstk[warp][cnt][lane] =
                                        (((unsigned long long)__float_as_uint(d)) << 32) | (unsigned)i;
                                cnt++;
                            }
                        }
                    }
                }
            }
            if (active) {
                int m = min(cnt, CAP);
                for (int i = 0; i < m; ++i) {
                    unsigned long long k = sm.f.sstk[warp][i][lane];
                    insert9(dk, ik, __uint_as_float((unsigned)(k >> 32)),
                            (int)(k & 0xffffffffULL));
                }
                ovf |= (cnt > CAP);
            }
        }

        unsigned long long mykey = INFKEY;
        if (active) {
            mykey = warp_merge9(dk, ik, lane);
            // safety: overflow or <9 survivors -> exact brute force (very rare)
            bool bad = (lane < KSEL) && ((unsigned)(mykey >> 32) >= 0x7f800000u);
            if (__ballot_sync(FULLMASK, ovf) || __ballot_sync(FULLMASK, bad)) {
#pragma unroll
                for (int j = 0; j < KSEL; ++j) { dk[j] = __int_as_float(0x7f800000); ik[j] = 0x7fffffff; }
                for (int n = lane; n < N; n += 32) {
                    float2 L = locs[n];
                    float dx = cx - L.x, dy = cy - L.y;
                    insert9(dk, ik, fmaf(dx, dx, dy * dy), n);
                }
                mykey = warp_merge9(dk, ik, lane);
            }

            // box losses + focal corrections for the 9 selected locations
            const int b = pair / G;
            float l1 = 0.0f, gl = 0.0f, delta = 0.0f;
            if (lane < KSEL) {
                int myN = (int)(mykey & 0xffffffffULL);
                float4 pb = pred_boxes[(long long)b * N + myN];
                l1 = fabsf(pb.x - gb.x) + fabsf(pb.y - gb.y)
                   + fabsf(pb.z - gb.z) + fabsf(pb.w - gb.w);

                float ax0 = pb.x - 0.5f * pb.z, ay0 = pb.y - 0.5f * pb.w;
                float ax1 = pb.x + 0.5f * pb.z, ay1 = pb.y + 0.5f * pb.w;
                float bx0 = gb.x - 0.5f * gb.z, by0 = gb.y - 0.5f * gb.w;
                float bx1 = gb.x + 0.5f * gb.z, by1 = gb.y + 0.5f * gb.w;

                float area_a = (ax1 - ax0) * (ay1 - ay0);
                float area_b = (bx1 - bx0) * (by1 - by0);
                float iw = fmaxf(fminf(ax1, bx1) - fmaxf(ax0, bx0), 0.0f);
                float ih = fmaxf(fminf(ay1, by1) - fmaxf(ay0, by0), 0.0f);
                float inter = iw * ih;
                float uni   = area_a + area_b - inter;
                float iou   = inter / uni;
                float cw = fmaxf(fmaxf(ax1, bx1) - fminf(ax0, bx0), 0.0f);
                float ch = fmaxf(fmaxf(ay1, by1) - fminf(ay0, by0), 0.0f);
                float areac = cw * ch;
                gl = 1.0f - (iou - (areac - uni) / areac);

                int lbl = gt_labels[pair];
                float x = logits[(long long)(b * N + myN) * C + lbl];
                delta = focal_t1(x) - focal_t0(x);
            }
#pragma unroll
            for (int off = 16; off > 0; off >>= 1) {
                l1    += __shfl_down_sync(FULLMASK, l1,    off);
                gl    += __shfl_down_sync(FULLMASK, gl,    off);
                delta += __shfl_down_sync(FULLMASK, delta, off);
            }
            if (lane == 0) {
                g_part_bbox [pair] = l1;
                g_part_giou [pair] = gl;
                g_part_delta[pair] = delta;
            }
        }
    }

    // ================= phase 2 (all blocks): uniform focal share ==============
    {
        const int per = (n4 + grid - 1) / grid;
        const int s   = bid * per;
        const int e   = min(n4, s + per);
        float acc = 0.0f;
        const float4* __restrict__ l4 = (const float4*)logits;
        for (int i = s + tid; i < e; i += TPB) {
            float4 v = l4[i];
            acc += focal_t0(v.x);
            acc += focal_t0(v.y);
            acc += focal_t0(v.z);
            acc += focal_t0(v.w);
        }
        if (bid == 0 && tid == 0) {
            for (int i = n4 * 4; i < total; ++i) acc += focal_t0(logits[i]);
        }
        __syncthreads();                  // smem union: done with pair data
        sm.red[tid] = acc;
        __syncthreads();
#pragma unroll
        for (int st = 128; st > 0; st >>= 1) {
            if (tid < st) sm.red[tid] += sm.red[tid + st];
            __syncthreads();
        }
        if (tid == 0) g_part_focal[bid] = sm.red[0];
    }

    // ================= phase 3: last block finalizes ==========================
    __threadfence();
    if (tid == 0) sticket = atomicAdd(&g_ctr, 1);
    __syncthreads();
    if (sticket == grid - 1) {
        double a0 = 0.0, a1 = 0.0, a2 = 0.0;
        for (int i = tid; i < grid; i += TPB) a0 += (double)g_part_focal[i];
        for (int i = tid; i < P; i += TPB) {
            a0 += (double)g_part_delta[i];
            a1 += (double)g_part_bbox [i];
            a2 += (double)g_part_giou [i];
        }
        sm.dred[0][tid] = a0;
        sm.dred[1][tid] = a1;
        sm.dred[2][tid] = a2;
        __syncthreads();
#pragma unroll
        for (int st = 128; st > 0; st >>= 1) {
            if (tid < st) {
                sm.dred[0][tid] += sm.dred[0][tid + st];
                sm.dred[1][tid] += sm.dred[1][tid + st];
                sm.dred[2][tid] += sm.dred[2][tid + st];
            }
            __syncthreads();
        }
        if (tid == 0) {
            out[0] = (float)(sm.dred[0][0] * invBNC);
            out[1] = (float)(sm.dred[1][0] * invBB);
            out[2] = (float)(sm.dred[2][0] * invGI);
            g_ctr  = 0;                   // self-reset for next graph replay
        }
    }
}

// ---------------- launch ----------------------------------------------------
extern "C" void kernel_launch(void* const* d_in, const int* in_sizes, int n_in,
                              void* d_out, int out_size)
{
    const float* logits = (const float*)d_in[0];   // (B,N,C)
    const float* pboxes = (const float*)d_in[1];   // (B,N,4)
    const float* locs   = (const float*)d_in[2];   // (N,2)
    const float* gboxes = (const float*)d_in[3];   // (B,G,4)
    const int*   glabel = (const int*)  d_in[4];   // (B,G)

    const int N = in_sizes[2] / 2;
    const int B = in_sizes[1] / (4 * N);
    const int C = in_sizes[0] / (B * N);
    const int G = in_sizes[4] / B;
    const int P = B * G;

    const int total = in_sizes[0];
    const int n4    = total / 4;

    int pairBlocks = (P + WARPS - 1) / WARPS;     // 128
    int grid = 4 * 148;                           // 4 CTAs/SM, full chip
    if (grid < pairBlocks) grid = pairBlocks;
    if (grid > 4096) grid = 4096;                 // g_part_focal capacity

    double invBNC = 1.0 / ((double)B * (double)N * (double)C);
    double invBB  = 1.0 / ((double)P * (double)KSEL * 4.0);
    double invGI  = 1.0 / ((double)P * (double)KSEL);

    fused_kernel<<<grid, TPB>>>(logits, (const float4*)pboxes,
                                (const float2*)locs, (const float4*)gboxes,
                                glabel, (float*)d_out,
                                B, N, C, G, pairBlocks,
                                n4, total, invBNC, invBB, invGI);
}

// round 13
// speedup vs baseline: 1.0752x; 1.0029x over previous
#include <cuda_runtime.h>
#include <math.h>

#define FULLMASK 0xffffffffu
#define KSEL   9
#define SEGS   4
#define CHUNK  1792
#define CAP    16
#define GATE2  0.0036f      /* (0.06)^2 — keeps true top-9 w.p. ~1-1e-14; exact fallback covers the rest */
#define WARPS  8
#define TPB    256
#define NB     1184         /* focal grid: 8 blocks/SM nominal */

#define INFKEY ((0x7f800000ULL << 32) | 0x7fffffffULL)

// ---------------- scratch (device globals; no allocation allowed) ----------
__device__ float g_part_focal[4096];
__device__ float g_part_bbox [4096];
__device__ float g_part_giou [4096];
__device__ float g_part_delta[4096];
__device__ int   g_ctr = 0;           // self-resetting completion counter

// ---------------- focal pieces ---------------------------------------------
__device__ __forceinline__ float focal_t0(float x) {
    float ax   = fabsf(x);
    float u    = __expf(-ax);
    float r    = __fdividef(1.0f, 1.0f + u);
    float prob = (x >= 0.0f) ? r : (1.0f - r);
    float sp   = fmaxf(x, 0.0f) + __logf(1.0f + u);
    return 0.75f * sp * (prob * prob);
}
__device__ __forceinline__ float focal_t1(float x) {
    float ax   = fabsf(x);
    float u    = __expf(-ax);
    float r    = __fdividef(1.0f, 1.0f + u);
    float prob = (x >= 0.0f) ? r : (1.0f - r);
    float q    = 1.0f - prob;
    float spn  = fmaxf(-x, 0.0f) + __logf(1.0f + u);
    return 0.25f * spn * (q * q);
}

// 8-wide batched focal_t0: stages MUFU ops in groups of 8 so the MUFU pipe
// sees 8 independent ops per thread instead of one 70-cycle chain.
__device__ __forceinline__ float focal8(float4 a, float4 b) {
    float x[8] = {a.x, a.y, a.z, a.w, b.x, b.y, b.z, b.w};
    float u[8], r[8], lg[8];
#pragma unroll
    for (int j = 0; j < 8; ++j) u[j]  = __expf(-fabsf(x[j]));
#pragma unroll
    for (int j = 0; j < 8; ++j) r[j]  = __fdividef(1.0f, 1.0f + u[j]);
#pragma unroll
    for (int j = 0; j < 8; ++j) lg[j] = __logf(1.0f + u[j]);
    float s = 0.0f;
#pragma unroll
    for (int j = 0; j < 8; ++j) {
        float prob = (x[j] >= 0.0f) ? r[j] : (1.0f - r[j]);
        float sp   = fmaxf(x[j], 0.0f) + lg[j];
        s += sp * (prob * prob);
    }
    return 0.75f * s;
}

// ---------------- top-9 helpers ---------------------------------------------
__device__ __forceinline__ void insert9(float (&dk)[KSEL], int (&ik)[KSEL],
                                        float d, int idx) {
    if (d < dk[KSEL - 1]) {
        dk[KSEL - 1] = d; ik[KSEL - 1] = idx;
#pragma unroll
        for (int j = KSEL - 1; j > 0; --j) {
            if (dk[j] < dk[j - 1]) {
                float td = dk[j]; dk[j] = dk[j - 1]; dk[j - 1] = td;
                int   ti = ik[j]; ik[j] = ik[j - 1]; ik[j - 1] = ti;
            }
        }
    }
}

__device__ __forceinline__ unsigned long long
warp_merge9(float (&dk)[KSEL], int (&ik)[KSEL], int lane) {
    unsigned long long mykey = INFKEY;
    unsigned long long key =
        (((unsigned long long)__float_as_uint(dk[0])) << 32) | (unsigned)ik[0];
#pragma unroll
    for (int r = 0; r < KSEL; ++r) {
        unsigned long long k = key;
#pragma unroll
        for (int off = 16; off > 0; off >>= 1) {
            unsigned long long o = __shfl_xor_sync(FULLMASK, k, off);
            k = (o < k) ? o : k;
        }
        if (lane == r) mykey = k;
        if (key == k) {
#pragma unroll
            for (int j = 0; j < KSEL - 1; ++j) { dk[j] = dk[j + 1]; ik[j] = ik[j + 1]; }
            dk[KSEL - 1] = __int_as_float(0x7f800000);
            ik[KSEL - 1] = 0x7fffffff;
            key = (((unsigned long long)__float_as_uint(dk[0])) << 32) | (unsigned)ik[0];
        }
    }
    return mykey;
}

// ---------------- K1: pair kernel (filter + top-9 + box losses) -------------
__global__ void __launch_bounds__(TPB)
pair_kernel(const float*  __restrict__ logits,
            const float4* __restrict__ pred_boxes,
            const float2* __restrict__ locs,
            const float4* __restrict__ gt_boxes,
            const int*    __restrict__ gt_labels,
            int B, int N, int C, int G)
{
    __shared__ __align__(16) float2 sloc[CHUNK];
    __shared__ unsigned long long sstk[WARPS][CAP][32];

    const int tid  = threadIdx.x;
    const int lane = tid & 31;
    const int warp = tid >> 5;
    const int pair = blockIdx.x * WARPS + warp;
    const int P    = B * G;
    const bool active = pair < P;

    float cx = 0.0f, cy = 0.0f;
    float4 gb = make_float4(0.f, 0.f, 0.f, 0.f);
    if (active) { gb = gt_boxes[pair]; cx = gb.x; cy = gb.y; }

    float dk[KSEL]; int ik[KSEL];
#pragma unroll
    for (int j = 0; j < KSEL; ++j) { dk[j] = __int_as_float(0x7f800000); ik[j] = 0x7fffffff; }
    bool ovf = false;

    const int segLen = (N + SEGS - 1) / SEGS;
    for (int seg = 0; seg < SEGS; ++seg) {
        const int s0 = seg * segLen;
        const int s1 = min(N, s0 + segLen);
        int cnt = 0;
        for (int base = s0; base < s1; base += CHUNK) {
            int c = min(CHUNK, s1 - base);
            __syncthreads();
            for (int i = tid; i < c; i += TPB) sloc[i] = locs[base + i];
            __syncthreads();
            if (active) {
                const float4* sl4 = (const float4*)sloc;
                int c2 = c >> 1;
                for (int j = lane; j < c2; j += 32) {
                    float4 v  = sl4[j];
                    float dx0 = cx - v.x, dy0 = cy - v.y;
                    float dx1 = cx - v.z, dy1 = cy - v.w;
                    float d0  = fmaf(dx0, dx0, dy0 * dy0);
                    float d1  = fmaf(dx1, dx1, dy1 * dy1);
                    int   i0  = base + 2 * j;
                    if (d0 <= GATE2) {
                        if (cnt < CAP)
                            sstk[warp][cnt][lane] =
                                (((unsigned long long)__float_as_uint(d0)) << 32) | (unsigned)i0;
                        cnt++;
                    }
                    if (d1 <= GATE2) {
                        if (cnt < CAP)
                            sstk[warp][cnt][lane] =
                                (((unsigned long long)__float_as_uint(d1)) << 32) | (unsigned)(i0 + 1);
                        cnt++;
                    }
                }
                if ((c & 1) != 0) {
                    int i = base + c - 1;
                    if (lane == (i & 31)) {
                        float2 L = sloc[c - 1];
                        float dx = cx - L.x, dy = cy - L.y;
                        float d  = fmaf(dx, dx, dy * dy);
                        if (d <= GATE2) {
                            if (cnt < CAP)
                                sstk[warp][cnt][lane] =
                                    (((unsigned long long)__float_as_uint(d)) << 32) | (unsigned)i;
                            cnt++;
                        }
                    }
                }
            }
        }
        if (active) {
            int m = min(cnt, CAP);
            for (int i = 0; i < m; ++i) {
                unsigned long long k = sstk[warp][i][lane];
                insert9(dk, ik, __uint_as_float((unsigned)(k >> 32)),
                        (int)(k & 0xffffffffULL));
            }
            ovf |= (cnt > CAP);
        }
    }

    if (!active) return;

    unsigned long long mykey = warp_merge9(dk, ik, lane);
    // safety: overflow or <9 survivors -> exact brute force (extremely rare)
    bool bad = (lane < KSEL) && ((unsigned)(mykey >> 32) >= 0x7f800000u);
    if (__ballot_sync(FULLMASK, ovf) || __ballot_sync(FULLMASK, bad)) {
#pragma unroll
        for (int j = 0; j < KSEL; ++j) { dk[j] = __int_as_float(0x7f800000); ik[j] = 0x7fffffff; }
        for (int n = lane; n < N; n += 32) {
            float2 L = locs[n];
            float dx = cx - L.x, dy = cy - L.y;
            insert9(dk, ik, fmaf(dx, dx, dy * dy), n);
        }
        mykey = warp_merge9(dk, ik, lane);
    }

    const int b = pair / G;
    float l1 = 0.0f, gl = 0.0f, delta = 0.0f;
    if (lane < KSEL) {
        int myN = (int)(mykey & 0xffffffffULL);
        float4 pb = pred_boxes[(long long)b * N + myN];
        l1 = fabsf(pb.x - gb.x) + fabsf(pb.y - gb.y)
           + fabsf(pb.z - gb.z) + fabsf(pb.w - gb.w);

        float ax0 = pb.x - 0.5f * pb.z, ay0 = pb.y - 0.5f * pb.w;
        float ax1 = pb.x + 0.5f * pb.z, ay1 = pb.y + 0.5f * pb.w;
        float bx0 = gb.x - 0.5f * gb.z, by0 = gb.y - 0.5f * gb.w;
        float bx1 = gb.x + 0.5f * gb.z, by1 = gb.y + 0.5f * gb.w;

        float area_a = (ax1 - ax0) * (ay1 - ay0);
        float area_b = (bx1 - bx0) * (by1 - by0);
        float iw = fmaxf(fminf(ax1, bx1) - fmaxf(ax0, bx0), 0.0f);
        float ih = fmaxf(fminf(ay1, by1) - fmaxf(ay0, by0), 0.0f);
        float inter = iw * ih;
        float uni   = area_a + area_b - inter;
        float iou   = inter / uni;
        float cw = fmaxf(fmaxf(ax1, bx1) - fminf(ax0, bx0), 0.0f);
        float ch = fmaxf(fmaxf(ay1, by1) - fminf(ay0, by0), 0.0f);
        float areac = cw * ch;
        gl = 1.0f - (iou - (areac - uni) / areac);

        int lbl = gt_labels[pair];
        float x = logits[(long long)(b * N + myN) * C + lbl];
        delta = focal_t1(x) - focal_t0(x);
    }
#pragma unroll
    for (int off = 16; off > 0; off >>= 1) {
        l1    += __shfl_down_sync(FULLMASK, l1,    off);
        gl    += __shfl_down_sync(FULLMASK, gl,    off);
        delta += __shfl_down_sync(FULLMASK, delta, off);
    }
    if (lane == 0) {
        g_part_bbox [pair] = l1;
        g_part_giou [pair] = gl;
        g_part_delta[pair] = delta;
    }
}

// ---------------- K2: focal base sum + last-block finalize -------------------
__global__ void __launch_bounds__(TPB)
focal_fin_kernel(const float* __restrict__ logits,
                 float* __restrict__ out,
                 int n8f, int total, int P,
                 double invBNC, double invBB, double invGI)
{
    __shared__ float  red[TPB];
    __shared__ double dred[3][TPB];
    __shared__ int    sticket;

    const int tid = threadIdx.x;
    const int bid = blockIdx.x;
    const int gid = bid * TPB + tid;
    const int stride = gridDim.x * TPB;
    const float4* __restrict__ l4 = (const float4*)logits;

    float acc = 0.0f;
    for (int p = gid; p < n8f; p += stride) {
        float4 a = l4[2 * p];
        float4 b = l4[2 * p + 1];
        acc += focal8(a, b);
    }
    if (bid == 0 && tid == 0) {
        for (int i = n8f * 8; i < total; ++i) acc += focal_t0(logits[i]);
    }

    red[tid] = acc;
    __syncthreads();
#pragma unroll
    for (int s = 128; s > 0; s >>= 1) {
        if (tid < s) red[tid] += red[tid + s];
        __syncthreads();
    }
    if (tid == 0) g_part_focal[bid] = red[0];

    // last block finalizes (deterministic fixed-order double sums)
    __threadfence();
    if (tid == 0) sticket = atomicAdd(&g_ctr, 1);
    __syncthreads();
    if (sticket == (int)gridDim.x - 1) {
        double a0 = 0.0, a1 = 0.0, a2 = 0.0;
        for (int i = tid; i < (int)gridDim.x; i += TPB) a0 += (double)g_part_focal[i];
        for (int i = tid; i < P; i += TPB) {
            a0 += (double)g_part_delta[i];
            a1 += (double)g_part_bbox [i];
            a2 += (double)g_part_giou [i];
        }
        dred[0][tid] = a0; dred[1][tid] = a1; dred[2][tid] = a2;
        __syncthreads();
#pragma unroll
        for (int s = 128; s > 0; s >>= 1) {
            if (tid < s) {
                dred[0][tid] += dred[0][tid + s];
                dred[1][tid] += dred[1][tid + s];
                dred[2][tid] += dred[2][tid + s];
            }
            __syncthreads();
        }
        if (tid == 0) {
            out[0] = (float)(dred[0][0] * invBNC);
            out[1] = (float)(dred[1][0] * invBB);
            out[2] = (float)(dred[2][0] * invGI);
            g_ctr  = 0;                   // self-reset for next graph replay
        }
    }
}

// ---------------- launch ----------------------------------------------------
extern "C" void kernel_launch(void* const* d_in, const int* in_sizes, int n_in,
                              void* d_out, int out_size)
{
    const float* logits = (const float*)d_in[0];   // (B,N,C)
    const float* pboxes = (const float*)d_in[1];   // (B,N,4)
    const float* locs   = (const float*)d_in[2];   // (N,2)
    const float* gboxes = (const float*)d_in[3];   // (B,G,4)
    const int*   glabel = (const int*)  d_in[4];   // (B,G)

    const int N = in_sizes[2] / 2;
    const int B = in_sizes[1] / (4 * N);
    const int C = in_sizes[0] / (B * N);
    const int G = in_sizes[4] / B;
    const int P = B * G;

    const int total = in_sizes[0];
    const int n8f   = total / 8;

    // K1: pairs (filter + top-9 + box losses), self-contained
    int blocks1 = (P + WARPS - 1) / WARPS;
    pair_kernel<<<blocks1, TPB>>>(logits, (const float4*)pboxes,
                                  (const float2*)locs, (const float4*)gboxes,
                                  glabel, B, N, C, G);

    // K2: focal base + finalize tail
    double invBNC = 1.0 / ((double)B * (double)N * (double)C);
    double invBB  = 1.0 / ((double)P * (double)KSEL * 4.0);
    double invGI  = 1.0 / ((double)P * (double)KSEL);
    focal_fin_kernel<<<NB, TPB>>>(logits, (float*)d_out, n8f, total, P,
                                  invBNC, invBB, invGI);
}

// round 14
// speedup vs baseline: 1.5023x; 1.3973x over previous
#include <cuda_runtime.h>
#include <math.h>

#define FULLMASK 0xffffffffu
#define KSEL    9
#define SEGS    4
#define CHUNK   1792
#define CAP     16
#define GATE2   0.0036f     /* (0.06)^2 — keeps true top-9 w.p. ~1-1e-14; exact fallback covers the rest */
#define WARPS   8
#define TPB     256
#define NSTEAL  592         /* focal stealer blocks: 4/SM * 148 */

#define INFKEY ((0x7f800000ULL << 32) | 0x7fffffffULL)

// ---------------- scratch (device globals; no allocation allowed) ----------
__device__ unsigned long long g_cand[4096 * SEGS * KSEL];
__device__ int                g_ovf [4096 * SEGS];
__device__ float g_part_focal[4096];   // per-TILE partials (tile-keyed => deterministic)
__device__ float g_part_bbox [4096];
__device__ float g_part_giou [4096];
__device__ float g_part_delta[4096];
__device__ int   g_tile = 0;           // work-steal counter (reset by finalize)
__device__ int   g_ctr  = 0;           // finalize ticket (reset by finalize)

// ---------------- packed f32x2 helpers --------------------------------------
__device__ __forceinline__ unsigned long long pk2(float lo, float hi) {
    unsigned long long r;
    asm("mov.b64 %0, {%1, %2};" : "=l"(r) : "f"(lo), "f"(hi));
    return r;
}
__device__ __forceinline__ void upk2(unsigned long long v, float& lo, float& hi) {
    asm("mov.b64 {%0, %1}, %2;" : "=f"(lo), "=f"(hi) : "l"(v));
}
__device__ __forceinline__ unsigned long long fma2_(unsigned long long a,
                                                    unsigned long long b,
                                                    unsigned long long c) {
    unsigned long long d;
    asm("fma.rn.f32x2 %0, %1, %2, %3;" : "=l"(d) : "l"(a), "l"(b), "l"(c));
    return d;
}
__device__ __forceinline__ unsigned long long mul2_(unsigned long long a,
                                                    unsigned long long b) {
    unsigned long long d;
    asm("mul.rn.f32x2 %0, %1, %2;" : "=l"(d) : "l"(a), "l"(b));
    return d;
}
__device__ __forceinline__ unsigned long long add2_(unsigned long long a,
                                                    unsigned long long b) {
    unsigned long long d;
    asm("add.rn.f32x2 %0, %1, %2;" : "=l"(d) : "l"(a), "l"(b));
    return d;
}
__device__ __forceinline__ unsigned long long dup2(float c) {
    unsigned u = __float_as_uint(c);
    return ((unsigned long long)u << 32) | (unsigned long long)u;
}

// ---------------- focal pieces ---------------------------------------------
__device__ __forceinline__ float focal_t0(float x) {
    float ax   = fabsf(x);
    float u    = __expf(-ax);
    float r    = __fdividef(1.0f, 1.0f + u);
    float prob = (x >= 0.0f) ? r : (1.0f - r);
    float sp   = fmaxf(x, 0.0f) + __logf(1.0f + u);
    return 0.75f * sp * (prob * prob);
}
__device__ __forceinline__ float focal_t1(float x) {
    float ax   = fabsf(x);
    float u    = __expf(-ax);
    float r    = __fdividef(1.0f, 1.0f + u);
    float prob = (x >= 0.0f) ? r : (1.0f - r);
    float q    = 1.0f - prob;
    float spn  = fmaxf(-x, 0.0f) + __logf(1.0f + u);
    return 0.25f * spn * (q * q);
}

// 8-wide focal_t0: batched MUFU (2/elem) + packed-f32x2 minimax log1p
// (A&S 4.1.44, |eps| <= 3e-8 on [0,1]).
__device__ __forceinline__ float focal8(float4 A, float4 B) {
    const unsigned long long C1 = dup2( 0.9999964239f);
    const unsigned long long C2 = dup2(-0.4998741238f);
    const unsigned long long C3 = dup2( 0.3317990258f);
    const unsigned long long C4 = dup2(-0.2407338084f);
    const unsigned long long C5 = dup2( 0.1676540711f);
    const unsigned long long C6 = dup2(-0.0953293897f);
    const unsigned long long C7 = dup2( 0.0360884937f);
    const unsigned long long C8 = dup2(-0.0064535442f);

    float x[8] = {A.x, A.y, A.z, A.w, B.x, B.y, B.z, B.w};
    float u[8], r[8];
#pragma unroll
    for (int j = 0; j < 8; ++j) u[j] = __expf(-fabsf(x[j]));
#pragma unroll
    for (int j = 0; j < 8; ++j) r[j] = __fdividef(1.0f, 1.0f + u[j]);

    unsigned long long ACC = 0ULL;   // packed (0.0f, 0.0f)
#pragma unroll
    for (int p = 0; p < 4; ++p) {
        float x0 = x[2 * p], x1 = x[2 * p + 1];
        unsigned long long U = pk2(u[2 * p], u[2 * p + 1]);
        unsigned long long t = fma2_(U, C8, C7);
        t = fma2_(t, U, C6);
        t = fma2_(t, U, C5);
        t = fma2_(t, U, C4);
        t = fma2_(t, U, C3);
        t = fma2_(t, U, C2);
        t = fma2_(t, U, C1);
        unsigned long long LG = mul2_(t, U);                 // log1p(u)
        unsigned long long SP = add2_(pk2(fmaxf(x0, 0.0f), fmaxf(x1, 0.0f)), LG);
        float p0 = (x0 >= 0.0f) ? r[2 * p]     : (1.0f - r[2 * p]);
        float p1 = (x1 >= 0.0f) ? r[2 * p + 1] : (1.0f - r[2 * p + 1]);
        unsigned long long PR = pk2(p0, p1);
        ACC = fma2_(SP, mul2_(PR, PR), ACC);
    }
    float lo, hi;
    upk2(ACC, lo, hi);
    return 0.75f * (lo + hi);
}

// ---------------- top-9 helpers ---------------------------------------------
__device__ __forceinline__ void insert9(float (&dk)[KSEL], int (&ik)[KSEL],
                                        float d, int idx) {
    if (d < dk[KSEL - 1]) {
        dk[KSEL - 1] = d; ik[KSEL - 1] = idx;
#pragma unroll
        for (int j = KSEL - 1; j > 0; --j) {
            if (dk[j] < dk[j - 1]) {
                float td = dk[j]; dk[j] = dk[j - 1]; dk[j - 1] = td;
                int   ti = ik[j]; ik[j] = ik[j - 1]; ik[j - 1] = ti;
            }
        }
    }
}

__device__ __forceinline__ unsigned long long
warp_merge9(float (&dk)[KSEL], int (&ik)[KSEL], int lane) {
    unsigned long long mykey = INFKEY;
    unsigned long long key =
        (((unsigned long long)__float_as_uint(dk[0])) << 32) | (unsigned)ik[0];
#pragma unroll
    for (int r = 0; r < KSEL; ++r) {
        unsigned long long k = key;
#pragma unroll
        for (int off = 16; off > 0; off >>= 1) {
            unsigned long long o = __shfl_xor_sync(FULLMASK, k, off);
            k = (o < k) ? o : k;
        }
        if (lane == r) mykey = k;
        if (key == k) {
#pragma unroll
            for (int j = 0; j < KSEL - 1; ++j) { dk[j] = dk[j + 1]; ik[j] = ik[j + 1]; }
            dk[KSEL - 1] = __int_as_float(0x7f800000);
            ik[KSEL - 1] = 0x7fffffff;
            key = (((unsigned long long)__float_as_uint(dk[0])) << 32) | (unsigned)ik[0];
        }
    }
    return mykey;
}

// ---------------- K1: role-split (filter blocks | focal stealer blocks) -----
__global__ void __launch_bounds__(TPB)
work_kernel(const float*  __restrict__ logits,
            const float2* __restrict__ locs,
            const float4* __restrict__ gt_boxes,
            int N, int P, int FB,
            int n8f, int total, int NT, int tileUnits)
{
    __shared__ __align__(16) union {
        struct {
            float2 sloc[CHUNK];                        // 14336 B
            unsigned long long sstk[WARPS][CAP][32];   // 32768 B
        } f;
        float red[32];
    } sm;
    __shared__ int stile;

    const int tid  = threadIdx.x;
    const int lane = tid & 31;
    const int warp = tid >> 5;
    const int bid  = blockIdx.x;

    if (bid < FB) {
        // ================= filter role (segment-parallel, as in R10) =========
        const int seg  = bid % SEGS;
        const int pair = (bid / SEGS) * WARPS + warp;
        const bool active = pair < P;

        float cx = 0.0f, cy = 0.0f;
        if (active) { float4 gb = gt_boxes[pair]; cx = gb.x; cy = gb.y; }

        const int segLen = (N + SEGS - 1) / SEGS;
        const int s0 = seg * segLen;
        const int s1 = min(N, s0 + segLen);

        int cnt = 0;
        for (int base = s0; base < s1; base += CHUNK) {
            int c = min(CHUNK, s1 - base);
            __syncthreads();
            for (int i = tid; i < c; i += TPB) sm.f.sloc[i] = locs[base + i];
            __syncthreads();
            if (active) {
                const float4* sl4 = (const float4*)sm.f.sloc;
                int c2 = c >> 1;
                for (int j = lane; j < c2; j += 32) {
                    float4 v  = sl4[j];
                    float dx0 = cx - v.x, dy0 = cy - v.y;
                    float dx1 = cx - v.z, dy1 = cy - v.w;
                    float d0  = fmaf(dx0, dx0, dy0 * dy0);
                    float d1  = fmaf(dx1, dx1, dy1 * dy1);
                    int   i0  = base + 2 * j;
                    if (d0 <= GATE2) {
                        if (cnt < CAP)
                            sm.f.sstk[warp][cnt][lane] =
                                (((unsigned long long)__float_as_uint(d0)) << 32) | (unsigned)i0;
                        cnt++;
                    }
                    if (d1 <= GATE2) {
                        if (cnt < CAP)
                            sm.f.sstk[warp][cnt][lane] =
                                (((unsigned long long)__float_as_uint(d1)) << 32) | (unsigned)(i0 + 1);
                        cnt++;
                    }
                }
                if ((c & 1) != 0) {
                    int i = base + c - 1;
                    if (lane == (i & 31)) {
                        float2 L = sm.f.sloc[c - 1];
                        float dx = cx - L.x, dy = cy - L.y;
                        float d  = fmaf(dx, dx, dy * dy);
                        if (d <= GATE2) {
                            if (cnt < CAP)
                                sm.f.sstk[warp][cnt][lane] =
                                    (((unsigned long long)__float_as_uint(d)) << 32) | (unsigned)i;
                            cnt++;
                        }
                    }
                }
            }
        }
        if (!active) return;

        float dk[KSEL]; int ik[KSEL];
#pragma unroll
        for (int j = 0; j < KSEL; ++j) { dk[j] = __int_as_float(0x7f800000); ik[j] = 0x7fffffff; }
        int m = min(cnt, CAP);
        for (int i = 0; i < m; ++i) {
            unsigned long long k = sm.f.sstk[warp][i][lane];
            insert9(dk, ik, __uint_as_float((unsigned)(k >> 32)),
                    (int)(k & 0xffffffffULL));
        }
        unsigned long long mykey = warp_merge9(dk, ik, lane);
        if (lane < KSEL) g_cand[(pair * SEGS + seg) * KSEL + lane] = mykey;
        int ovf = __ballot_sync(FULLMASK, cnt > CAP);
        if (lane == 0) g_ovf[pair * SEGS + seg] = (ovf != 0);
        return;   // filter blocks retire; their SM slots refill with stealers
    }

    // ================= focal stealer role =====================================
    const float4* __restrict__ l4 = (const float4*)logits;
    const int itersPerTile = tileUnits / TPB;
    for (;;) {
        if (tid == 0) stile = atomicAdd(&g_tile, 1);
        __syncthreads();
        const int t = stile;
        if (t >= NT) break;

        const int base = t * tileUnits;
        float acc = 0.0f;
        for (int k = 0; k < itersPerTile; ++k) {
            int u = base + k * TPB + tid;
            if (u < n8f) {
                float4 a = l4[2 * u];
                float4 b = l4[2 * u + 1];
                acc += focal8(a, b);
            }
        }
        if (t == NT - 1 && tid == 0) {   // scalar tail (deterministic: tile-keyed)
            for (int i = n8f * 8; i < total; ++i) acc += focal_t0(logits[i]);
        }

        // fixed-order block reduction -> per-tile partial (deterministic)
#pragma unroll
        for (int off = 16; off > 0; off >>= 1)
            acc += __shfl_down_sync(FULLMASK, acc, off);
        if (lane == 0) sm.red[warp] = acc;
        __syncthreads();
        if (warp == 0) {
            float v = (lane < WARPS) ? sm.red[lane] : 0.0f;
#pragma unroll
            for (int off = 4; off > 0; off >>= 1)
                v += __shfl_down_sync(FULLMASK, v, off);
            if (lane == 0) g_part_focal[t] = v;
        }
        __syncthreads();   // protects sm.red and stile reuse
    }
}

// ---------------- K2: merge + box losses + finalize tail --------------------
__global__ void __launch_bounds__(TPB)
merge_fin_kernel(const float*  __restrict__ logits,
                 const float4* __restrict__ pred_boxes,
                 const float2* __restrict__ locs,
                 const float4* __restrict__ gt_boxes,
                 const int*    __restrict__ gt_labels,
                 float* __restrict__ out,
                 int B, int N, int C, int G, int NT,
                 double invBNC, double invBB, double invGI)
{
    __shared__ double dred[3][TPB];
    __shared__ int sticket;

    const int tid  = threadIdx.x;
    const int lane = tid & 31;
    const int warp = tid >> 5;
    const int pair = blockIdx.x * WARPS + warp;
    const int P    = B * G;

    if (pair < P) {
        // load SEGS*KSEL = 36 candidate keys, 2 per lane, pre-sorted pair
        unsigned long long k0 = INFKEY, k1 = INFKEY;
        if (lane      < SEGS * KSEL) k0 = g_cand[pair * SEGS * KSEL + lane];
        if (lane + 32 < SEGS * KSEL) k1 = g_cand[pair * SEGS * KSEL + lane + 32];
        if (k1 < k0) { unsigned long long t = k0; k0 = k1; k1 = t; }

        unsigned long long mykey = INFKEY;
#pragma unroll
        for (int r = 0; r < KSEL; ++r) {
            unsigned long long k = k0;
#pragma unroll
            for (int off = 16; off > 0; off >>= 1) {
                unsigned long long o = __shfl_xor_sync(FULLMASK, k, off);
                k = (o < k) ? o : k;
            }
            if (lane == r) mykey = k;
            if (k0 == k) { k0 = k1; k1 = INFKEY; }
        }

        // safety: overflow or <9 survivors -> exact brute force (extremely rare)
        int ovf = 0;
        for (int s = 0; s < SEGS; ++s) ovf |= g_ovf[pair * SEGS + s];
        bool bad = (lane < KSEL) && ((unsigned)(mykey >> 32) >= 0x7f800000u);
        float4 gb = gt_boxes[pair];
        if (ovf || __ballot_sync(FULLMASK, bad)) {
            float dk[KSEL]; int ik[KSEL];
#pragma unroll
            for (int j = 0; j < KSEL; ++j) { dk[j] = __int_as_float(0x7f800000); ik[j] = 0x7fffffff; }
            for (int n = lane; n < N; n += 32) {
                float2 L = locs[n];
                float dx = gb.x - L.x, dy = gb.y - L.y;
                insert9(dk, ik, fmaf(dx, dx, dy * dy), n);
            }
            mykey = warp_merge9(dk, ik, lane);
        }

        const int b = pair / G;
        float l1 = 0.0f, gl = 0.0f, delta = 0.0f;
        if (lane < KSEL) {
            int myN = (int)(mykey & 0xffffffffULL);
            float4 pb = pred_boxes[(long long)b * N + myN];
            l1 = fabsf(pb.x - gb.x) + fabsf(pb.y - gb.y)
               + fabsf(pb.z - gb.z) + fabsf(pb.w - gb.w);

            float ax0 = pb.x - 0.5f * pb.z, ay0 = pb.y - 0.5f * pb.w;
            float ax1 = pb.x + 0.5f * pb.z, ay1 = pb.y + 0.5f * pb.w;
            float bx0 = gb.x - 0.5f * gb.z, by0 = gb.y - 0.5f * gb.w;
            float bx1 = gb.x + 0.5f * gb.z, by1 = gb.y + 0.5f * gb.w;

            float area_a = (ax1 - ax0) * (ay1 - ay0);
            float area_b = (bx1 - bx0) * (by1 - by0);
            float iw = fmaxf(fminf(ax1, bx1) - fmaxf(ax0, bx0), 0.0f);
            float ih = fmaxf(fminf(ay1, by1) - fmaxf(ay0, by0), 0.0f);
            float inter = iw * ih;
            float uni   = area_a + area_b - inter;
            float iou   = inter / uni;
            float cw = fmaxf(fmaxf(ax1, bx1) - fminf(ax0, bx0), 0.0f);
            float ch = fmaxf(fmaxf(ay1, by1) - fminf(ay0, by0), 0.0f);
            float areac = cw * ch;
            gl = 1.0f - (iou - (areac - uni) / areac);

            int lbl = gt_labels[pair];
            float x = logits[(long long)(b * N + myN) * C + lbl];
            delta = focal_t1(x) - focal_t0(x);
        }
#pragma unroll
        for (int off = 16; off > 0; off >>= 1) {
            l1    += __shfl_down_sync(FULLMASK, l1,    off);
            gl    += __shfl_down_sync(FULLMASK, gl,    off);
            delta += __shfl_down_sync(FULLMASK, delta, off);
        }
        if (lane == 0) {
            g_part_bbox [pair] = l1;
            g_part_giou [pair] = gl;
            g_part_delta[pair] = delta;
        }
    }

    // last block finalizes (deterministic fixed-order double sums)
    __threadfence();
    __syncthreads();
    if (tid == 0) sticket = atomicAdd(&g_ctr, 1);
    __syncthreads();
    if (sticket == (int)gridDim.x - 1) {
        double a0 = 0.0, a1 = 0.0, a2 = 0.0;
        for (int i = tid; i < NT; i += TPB) a0 += (double)g_part_focal[i];
        for (int i = tid; i < P; i += TPB) {
            a0 += (double)g_part_delta[i];
            a1 += (double)g_part_bbox [i];
            a2 += (double)g_part_giou [i];
        }
        dred[0][tid] = a0; dred[1][tid] = a1; dred[2][tid] = a2;
        __syncthreads();
#pragma unroll
        for (int s = 128; s > 0; s >>= 1) {
            if (tid < s) {
                dred[0][tid] += dred[0][tid + s];
                dred[1][tid] += dred[1][tid + s];
                dred[2][tid] += dred[2][tid + s];
            }
            __syncthreads();
        }
        if (tid == 0) {
            out[0] = (float)(dred[0][0] * invBNC);
            out[1] = (float)(dred[1][0] * invBB);
            out[2] = (float)(dred[2][0] * invGI);
            g_ctr  = 0;     // self-reset for next graph replay
            g_tile = 0;
        }
    }
}

// ---------------- launch ----------------------------------------------------
extern "C" void kernel_launch(void* const* d_in, const int* in_sizes, int n_in,
                              void* d_out, int out_size)
{
    const float* logits = (const float*)d_in[0];   // (B,N,C)
    const float* pboxes = (const float*)d_in[1];   // (B,N,4)
    const float* locs   = (const float*)d_in[2];   // (N,2)
    const float* gboxes = (const float*)d_in[3];   // (B,G,4)
    const int*   glabel = (const int*)  d_in[4];   // (B,G)

    const int N = in_sizes[2] / 2;
    const int B = in_sizes[1] / (4 * N);
    const int C = in_sizes[0] / (B * N);
    const int G = in_sizes[4] / B;
    const int P = B * G;

    const int total = in_sizes[0];
    const int n8f   = total / 8;

    // focal tiling (tile-keyed partials; NT must fit g_part_focal)
    int tileUnits = 1024;                      // 4 iterations of 256 threads
    int NT = (n8f + tileUnits - 1) / tileUnits;
    while (NT > 4096) { tileUnits *= 2; NT = (n8f + tileUnits - 1) / tileUnits; }

    const int FB    = ((P + WARPS - 1) / WARPS) * SEGS;   // 512 filter blocks
    const int grid1 = FB + NSTEAL;

    work_kernel<<<grid1, TPB>>>(logits, (const float2*)locs,
                                (const float4*)gboxes,
                                N, P, FB, n8f, total, NT, tileUnits);

    double invBNC = 1.0 / ((double)B * (double)N * (double)C);
    double invBB  = 1.0 / ((double)P * (double)KSEL * 4.0);
    double invGI  = 1.0 / ((double)P * (double)KSEL);

    int grid2 = (P + WARPS - 1) / WARPS;       // 128
    merge_fin_kernel<<<grid2, TPB>>>(logits, (const float4*)pboxes,
                                     (const float2*)locs, (const float4*)gboxes,
                                     glabel, (float*)d_out,
                                     B, N, C, G, NT, invBNC, invBB, invGI);
}

// round 15
// speedup vs baseline: 1.5667x; 1.0429x over previous
#include <cuda_runtime.h>
#include <math.h>

#define FULLMASK 0xffffffffu
#define KSEL    9
#define SEGS    4
#define CHUNK   1792
#define CAP     16
#define GATE2   0.0036f     /* (0.06)^2 — keeps true top-9 w.p. ~1-1e-14; exact fallback covers the rest */
#define WARPS   8
#define TPB     256

#define INFKEY ((0x7f800000ULL << 32) | 0x7fffffffULL)

// ---------------- scratch (device globals; no allocation allowed) ----------
__device__ unsigned long long g_cand[4096 * SEGS * KSEL];
__device__ int                g_ovf [4096 * SEGS];
__device__ float g_part_focal[4096];   // per-TILE partials (tile-keyed => deterministic)
__device__ float g_part_bbox [4096];
__device__ float g_part_giou [4096];
__device__ float g_part_delta[4096];
__device__ int   g_tile  = 0;          // focal work-steal counter
__device__ int   g_fdone = 0;          // filter-completion counter
__device__ int   g_ctr   = 0;          // finalize ticket

// ---------------- packed f32x2 helpers --------------------------------------
__device__ __forceinline__ unsigned long long pk2(float lo, float hi) {
    unsigned long long r;
    asm("mov.b64 %0, {%1, %2};" : "=l"(r) : "f"(lo), "f"(hi));
    return r;
}
__device__ __forceinline__ void upk2(unsigned long long v, float& lo, float& hi) {
    asm("mov.b64 {%0, %1}, %2;" : "=f"(lo), "=f"(hi) : "l"(v));
}
__device__ __forceinline__ unsigned long long fma2_(unsigned long long a,
                                                    unsigned long long b,
                                                    unsigned long long c) {
    unsigned long long d;
    asm("fma.rn.f32x2 %0, %1, %2, %3;" : "=l"(d) : "l"(a), "l"(b), "l"(c));
    return d;
}
__device__ __forceinline__ unsigned long long mul2_(unsigned long long a,
                                                    unsigned long long b) {
    unsigned long long d;
    asm("mul.rn.f32x2 %0, %1, %2;" : "=l"(d) : "l"(a), "l"(b));
    return d;
}
__device__ __forceinline__ unsigned long long add2_(unsigned long long a,
                                                    unsigned long long b) {
    unsigned long long d;
    asm("add.rn.f32x2 %0, %1, %2;" : "=l"(d) : "l"(a), "l"(b));
    return d;
}
__device__ __forceinline__ unsigned long long dup2(float c) {
    unsigned u = __float_as_uint(c);
    return ((unsigned long long)u << 32) | (unsigned long long)u;
}

// ---------------- focal pieces ---------------------------------------------
__device__ __forceinline__ float focal_t0(float x) {
    float ax   = fabsf(x);
    float u    = __expf(-ax);
    float r    = __fdividef(1.0f, 1.0f + u);
    float prob = (x >= 0.0f) ? r : (1.0f - r);
    float sp   = fmaxf(x, 0.0f) + __logf(1.0f + u);
    return 0.75f * sp * (prob * prob);
}
__device__ __forceinline__ float focal_t1(float x) {
    float ax   = fabsf(x);
    float u    = __expf(-ax);
    float r    = __fdividef(1.0f, 1.0f + u);
    float prob = (x >= 0.0f) ? r : (1.0f - r);
    float q    = 1.0f - prob;
    float spn  = fmaxf(-x, 0.0f) + __logf(1.0f + u);
    return 0.25f * spn * (q * q);
}

// 8-wide focal_t0: batched MUFU (2/elem) + packed-f32x2 minimax log1p
// (A&S 4.1.44, |eps| <= 3e-8 on [0,1]).
__device__ __forceinline__ float focal8(float4 A, float4 B) {
    const unsigned long long C1 = dup2( 0.9999964239f);
    const unsigned long long C2 = dup2(-0.4998741238f);
    const unsigned long long C3 = dup2( 0.3317990258f);
    const unsigned long long C4 = dup2(-0.2407338084f);
    const unsigned long long C5 = dup2( 0.1676540711f);
    const unsigned long long C6 = dup2(-0.0953293897f);
    const unsigned long long C7 = dup2( 0.0360884937f);
    const unsigned long long C8 = dup2(-0.0064535442f);

    float x[8] = {A.x, A.y, A.z, A.w, B.x, B.y, B.z, B.w};
    float u[8], r[8];
#pragma unroll
    for (int j = 0; j < 8; ++j) u[j] = __expf(-fabsf(x[j]));
#pragma unroll
    for (int j = 0; j < 8; ++j) r[j] = __fdividef(1.0f, 1.0f + u[j]);

    unsigned long long ACC = 0ULL;   // packed (0.0f, 0.0f)
#pragma unroll
    for (int p = 0; p < 4; ++p) {
        float x0 = x[2 * p], x1 = x[2 * p + 1];
        unsigned long long U = pk2(u[2 * p], u[2 * p + 1]);
        unsigned long long t = fma2_(U, C8, C7);
        t = fma2_(t, U, C6);
        t = fma2_(t, U, C5);
        t = fma2_(t, U, C4);
        t = fma2_(t, U, C3);
        t = fma2_(t, U, C2);
        t = fma2_(t, U, C1);
        unsigned long long LG = mul2_(t, U);                 // log1p(u)
        unsigned long long SP = add2_(pk2(fmaxf(x0, 0.0f), fmaxf(x1, 0.0f)), LG);
        float p0 = (x0 >= 0.0f) ? r[2 * p]     : (1.0f - r[2 * p]);
        float p1 = (x1 >= 0.0f) ? r[2 * p + 1] : (1.0f - r[2 * p + 1]);
        unsigned long long PR = pk2(p0, p1);
        ACC = fma2_(SP, mul2_(PR, PR), ACC);
    }
    float lo, hi;
    upk2(ACC, lo, hi);
    return 0.75f * (lo + hi);
}

// ---------------- top-9 helpers ---------------------------------------------
__device__ __forceinline__ void insert9(float (&dk)[KSEL], int (&ik)[KSEL],
                                        float d, int idx) {
    if (d < dk[KSEL - 1]) {
        dk[KSEL - 1] = d; ik[KSEL - 1] = idx;
#pragma unroll
        for (int j = KSEL - 1; j > 0; --j) {
            if (dk[j] < dk[j - 1]) {
                float td = dk[j]; dk[j] = dk[j - 1]; dk[j - 1] = td;
                int   ti = ik[j]; ik[j] = ik[j - 1]; ik[j - 1] = ti;
            }
        }
    }
}

__device__ __forceinline__ unsigned long long
warp_merge9(float (&dk)[KSEL], int (&ik)[KSEL], int lane) {
    unsigned long long mykey = INFKEY;
    unsigned long long key =
        (((unsigned long long)__float_as_uint(dk[0])) << 32) | (unsigned)ik[0];
#pragma unroll
    for (int r = 0; r < KSEL; ++r) {
        unsigned long long k = key;
#pragma unroll
        for (int off = 16; off > 0; off >>= 1) {
            unsigned long long o = __shfl_xor_sync(FULLMASK, k, off);
            k = (o < k) ? o : k;
        }
        if (lane == r) mykey = k;
        if (key == k) {
#pragma unroll
            for (int j = 0; j < KSEL - 1; ++j) { dk[j] = dk[j + 1]; ik[j] = ik[j + 1]; }
            dk[KSEL - 1] = __int_as_float(0x7f800000);
            ik[KSEL - 1] = 0x7fffffff;
            key = (((unsigned long long)__float_as_uint(dk[0])) << 32) | (unsigned)ik[0];
        }
    }
    return mykey;
}

// ---------------- THE kernel: filter -> focal steal -> merge -> finalize ----
__global__ void __launch_bounds__(TPB, 4)
mega_kernel(const float*  __restrict__ logits,
            const float4* __restrict__ pred_boxes,
            const float2* __restrict__ locs,
            const float4* __restrict__ gt_boxes,
            const int*    __restrict__ gt_labels,
            float* __restrict__ out,
            int B, int N, int C, int G, int FB, int MB,
            int n8f, int total, int NT, int tileUnits,
            double invBNC, double invBB, double invGI)
{
    __shared__ __align__(16) union {
        struct {
            float2 sloc[CHUNK];                        // 14336 B
            unsigned long long sstk[WARPS][CAP][32];   // 32768 B
        } f;
        float  red[32];
        double dred[3][TPB];
    } sm;
    __shared__ int stile;
    __shared__ int sticket;

    const int tid  = threadIdx.x;
    const int lane = tid & 31;
    const int warp = tid >> 5;
    const int bid  = blockIdx.x;
    const int P    = B * G;

    // ================= role 1 (bids < FB): segment filter =====================
    if (bid < FB) {
        const int seg  = bid % SEGS;
        const int pair = (bid / SEGS) * WARPS + warp;
        const bool active = pair < P;

        float cx = 0.0f, cy = 0.0f;
        if (active) { float4 gb = gt_boxes[pair]; cx = gb.x; cy = gb.y; }

        const int segLen = (N + SEGS - 1) / SEGS;
        const int s0 = seg * segLen;
        const int s1 = min(N, s0 + segLen);

        int cnt = 0;
        for (int base = s0; base < s1; base += CHUNK) {
            int c = min(CHUNK, s1 - base);
            __syncthreads();
            for (int i = tid; i < c; i += TPB) sm.f.sloc[i] = locs[base + i];
            __syncthreads();
            if (active) {
                const float4* sl4 = (const float4*)sm.f.sloc;
                int c2 = c >> 1;
                for (int j = lane; j < c2; j += 32) {
                    float4 v  = sl4[j];
                    float dx0 = cx - v.x, dy0 = cy - v.y;
                    float dx1 = cx - v.z, dy1 = cy - v.w;
                    float d0  = fmaf(dx0, dx0, dy0 * dy0);
                    float d1  = fmaf(dx1, dx1, dy1 * dy1);
                    int   i0  = base + 2 * j;
                    if (d0 <= GATE2) {
                        if (cnt < CAP)
                            sm.f.sstk[warp][cnt][lane] =
                                (((unsigned long long)__float_as_uint(d0)) << 32) | (unsigned)i0;
                        cnt++;
                    }
                    if (d1 <= GATE2) {
                        if (cnt < CAP)
                            sm.f.sstk[warp][cnt][lane] =
                                (((unsigned long long)__float_as_uint(d1)) << 32) | (unsigned)(i0 + 1);
                        cnt++;
                    }
                }
                if ((c & 1) != 0) {
                    int i = base + c - 1;
                    if (lane == (i & 31)) {
                        float2 L = sm.f.sloc[c - 1];
                        float dx = cx - L.x, dy = cy - L.y;
                        float d  = fmaf(dx, dx, dy * dy);
                        if (d <= GATE2) {
                            if (cnt < CAP)
                                sm.f.sstk[warp][cnt][lane] =
                                    (((unsigned long long)__float_as_uint(d)) << 32) | (unsigned)i;
                            cnt++;
                        }
                    }
                }
            }
        }
        if (active) {
            float dk[KSEL]; int ik[KSEL];
#pragma unroll
            for (int j = 0; j < KSEL; ++j) { dk[j] = __int_as_float(0x7f800000); ik[j] = 0x7fffffff; }
            int m = min(cnt, CAP);
            for (int i = 0; i < m; ++i) {
                unsigned long long k = sm.f.sstk[warp][i][lane];
                insert9(dk, ik, __uint_as_float((unsigned)(k >> 32)),
                        (int)(k & 0xffffffffULL));
            }
            unsigned long long mykey = warp_merge9(dk, ik, lane);
            if (lane < KSEL) g_cand[(pair * SEGS + seg) * KSEL + lane] = mykey;
            int ovf = __ballot_sync(FULLMASK, cnt > CAP);
            if (lane == 0) g_ovf[pair * SEGS + seg] = (ovf != 0);
        }
        __syncthreads();            // all warps' results written
        __threadfence();
        if (tid == 0) atomicAdd(&g_fdone, 1);
        // fall through: join the focal steal pool
    }

    // ================= role 2 (ALL blocks): focal tile stealing ===============
    {
        const float4* __restrict__ l4 = (const float4*)logits;
        const int itersPerTile = tileUnits / TPB;
        for (;;) {
            __syncthreads();        // protects sm union + stile reuse
            if (tid == 0) stile = atomicAdd(&g_tile, 1);
            __syncthreads();
            const int t = stile;
            if (t >= NT) break;

            const int base = t * tileUnits;
            float acc = 0.0f;
            for (int k = 0; k < itersPerTile; ++k) {
                int u = base + k * TPB + tid;
                if (u < n8f) {
                    float4 a = l4[2 * u];
                    float4 b = l4[2 * u + 1];
                    acc += focal8(a, b);
                }
            }
            if (t == NT - 1 && tid == 0) {   // scalar tail (tile-keyed => deterministic)
                for (int i = n8f * 8; i < total; ++i) acc += focal_t0(logits[i]);
            }
#pragma unroll
            for (int off = 16; off > 0; off >>= 1)
                acc += __shfl_down_sync(FULLMASK, acc, off);
            if (lane == 0) sm.red[warp] = acc;
            __syncthreads();
            if (warp == 0) {
                float v = (lane < WARPS) ? sm.red[lane] : 0.0f;
#pragma unroll
                for (int off = 4; off > 0; off >>= 1)
                    v += __shfl_down_sync(FULLMASK, v, off);
                if (lane == 0) g_part_focal[t] = v;
            }
        }
    }

    // ================= role 3 (bids < MB): merge + box losses =================
    if (bid < MB) {
        if (tid == 0) {             // expected 0 iterations: focal outlives filters
            while (atomicAdd(&g_fdone, 0) < FB) __nanosleep(128);
        }
        __syncthreads();
        __threadfence();

        const int pair = bid * WARPS + warp;
        if (pair < P) {
            unsigned long long k0 = INFKEY, k1 = INFKEY;
            if (lane      < SEGS * KSEL) k0 = g_cand[pair * SEGS * KSEL + lane];
            if (lane + 32 < SEGS * KSEL) k1 = g_cand[pair * SEGS * KSEL + lane + 32];
            if (k1 < k0) { unsigned long long t = k0; k0 = k1; k1 = t; }

            unsigned long long mykey = INFKEY;
#pragma unroll
            for (int r = 0; r < KSEL; ++r) {
                unsigned long long k = k0;
#pragma unroll
                for (int off = 16; off > 0; off >>= 1) {
                    unsigned long long o = __shfl_xor_sync(FULLMASK, k, off);
                    k = (o < k) ? o : k;
                }
                if (lane == r) mykey = k;
                if (k0 == k) { k0 = k1; k1 = INFKEY; }
            }

            int ovf = 0;
            for (int s = 0; s < SEGS; ++s) ovf |= g_ovf[pair * SEGS + s];
            bool bad = (lane < KSEL) && ((unsigned)(mykey >> 32) >= 0x7f800000u);
            float4 gb = gt_boxes[pair];
            if (ovf || __ballot_sync(FULLMASK, bad)) {   // exact fallback (rare)
                float dk[KSEL]; int ik[KSEL];
#pragma unroll
                for (int j = 0; j < KSEL; ++j) { dk[j] = __int_as_float(0x7f800000); ik[j] = 0x7fffffff; }
                for (int n = lane; n < N; n += 32) {
                    float2 L = locs[n];
                    float dx = gb.x - L.x, dy = gb.y - L.y;
                    insert9(dk, ik, fmaf(dx, dx, dy * dy), n);
                }
                mykey = warp_merge9(dk, ik, lane);
            }

            const int b = pair / G;
            float l1 = 0.0f, gl = 0.0f, delta = 0.0f;
            if (lane < KSEL) {
                int myN = (int)(mykey & 0xffffffffULL);
                float4 pb = pred_boxes[(long long)b * N + myN];
                l1 = fabsf(pb.x - gb.x) + fabsf(pb.y - gb.y)
                   + fabsf(pb.z - gb.z) + fabsf(pb.w - gb.w);

                float ax0 = pb.x - 0.5f * pb.z, ay0 = pb.y - 0.5f * pb.w;
                float ax1 = pb.x + 0.5f * pb.z, ay1 = pb.y + 0.5f * pb.w;
                float bx0 = gb.x - 0.5f * gb.z, by0 = gb.y - 0.5f * gb.w;
                float bx1 = gb.x + 0.5f * gb.z, by1 = gb.y + 0.5f * gb.w;

                float area_a = (ax1 - ax0) * (ay1 - ay0);
                float area_b = (bx1 - bx0) * (by1 - by0);
                float iw = fmaxf(fminf(ax1, bx1) - fmaxf(ax0, bx0), 0.0f);
                float ih = fmaxf(fminf(ay1, by1) - fmaxf(ay0, by0), 0.0f);
                float inter = iw * ih;
                float uni   = area_a + area_b - inter;
                float iou   = inter / uni;
                float cw = fmaxf(fmaxf(ax1, bx1) - fminf(ax0, bx0), 0.0f);
                float ch = fmaxf(fmaxf(ay1, by1) - fminf(ay0, by0), 0.0f);
                float areac = cw * ch;
                gl = 1.0f - (iou - (areac - uni) / areac);

                int lbl = gt_labels[pair];
                float x = logits[(long long)(b * N + myN) * C + lbl];
                delta = focal_t1(x) - focal_t0(x);
            }
#pragma unroll
            for (int off = 16; off > 0; off >>= 1) {
                l1    += __shfl_down_sync(FULLMASK, l1,    off);
                gl    += __shfl_down_sync(FULLMASK, gl,    off);
                delta += __shfl_down_sync(FULLMASK, delta, off);
            }
            if (lane == 0) {
                g_part_bbox [pair] = l1;
                g_part_giou [pair] = gl;
                g_part_delta[pair] = delta;
            }
        }
    }

    // ================= role 4: last block finalizes ===========================
    __threadfence();
    __syncthreads();
    if (tid == 0) sticket = atomicAdd(&g_ctr, 1);
    __syncthreads();
    if (sticket == (int)gridDim.x - 1) {
        double a0 = 0.0, a1 = 0.0, a2 = 0.0;
        for (int i = tid; i < NT; i += TPB) a0 += (double)g_part_focal[i];
        for (int i = tid; i < P; i += TPB) {
            a0 += (double)g_part_delta[i];
            a1 += (double)g_part_bbox [i];
            a2 += (double)g_part_giou [i];
        }
        sm.dred[0][tid] = a0; sm.dred[1][tid] = a1; sm.dred[2][tid] = a2;
        __syncthreads();
#pragma unroll
        for (int s = 128; s > 0; s >>= 1) {
            if (tid < s) {
                sm.dred[0][tid] += sm.dred[0][tid + s];
                sm.dred[1][tid] += sm.dred[1][tid + s];
                sm.dred[2][tid] += sm.dred[2][tid + s];
            }
            __syncthreads();
        }
        if (tid == 0) {
            out[0] = (float)(sm.dred[0][0] * invBNC);
            out[1] = (float)(sm.dred[1][0] * invBB);
            out[2] = (float)(sm.dred[2][0] * invGI);
            g_ctr   = 0;    // self-reset for next graph replay
            g_tile  = 0;
            g_fdone = 0;
        }
    }
}

// ---------------- launch ----------------------------------------------------
extern "C" void kernel_launch(void* const* d_in, const int* in_sizes, int n_in,
                              void* d_out, int out_size)
{
    const float* logits = (const float*)d_in[0];   // (B,N,C)
    const float* pboxes = (const float*)d_in[1];   // (B,N,4)
    const float* locs   = (const float*)d_in[2];   // (N,2)
    const float* gboxes = (const float*)d_in[3];   // (B,G,4)
    const int*   glabel = (const int*)  d_in[4];   // (B,G)

    const int N = in_sizes[2] / 2;
    const int B = in_sizes[1] / (4 * N);
    const int C = in_sizes[0] / (B * N);
    const int G = in_sizes[4] / B;
    const int P = B * G;

    const int total = in_sizes[0];
    const int n8f   = total / 8;

    // focal tiling (tile-keyed partials; NT must fit g_part_focal)
    int tileUnits = 2048;                      // 8 iterations of 256 threads
    int NT = (n8f + tileUnits - 1) / tileUnits;
    while (NT > 4096) { tileUnits *= 2; NT = (n8f + tileUnits - 1) / tileUnits; }

    const int MB = (P + WARPS - 1) / WARPS;    // 128 merge blocks
    const int FB = MB * SEGS;                  // 512 filter blocks
    int grid = FB + 96;                        // + early focal stealers
    if (grid < MB + 1) grid = MB + 1;          // spin-safety: non-spinners exist

    double invBNC = 1.0 / ((double)B * (double)N * (double)C);
    double invBB  = 1.0 / ((double)P * (double)KSEL * 4.0);
    double invGI  = 1.0 / ((double)P * (double)KSEL);

    mega_kernel<<<grid, TPB>>>(logits, (const float4*)pboxes,
                               (const float2*)locs, (const float4*)gboxes,
                               glabel, (float*)d_out,
                               B, N, C, G, FB, MB,
                               n8f, total, NT, tileUnits,
                               invBNC, invBB, invGI);
}

// round 16
// speedup vs baseline: 1.8483x; 1.1798x over previous
#include <cuda_runtime.h>
#include <math.h>

#define FULLMASK 0xffffffffu
#define KSEL    9
#define SEGS    4
#define CHUNK   1792
#define CAP     16
#define GATE2   0.0036f     /* (0.06)^2 — keeps true top-9 w.p. ~1-1e-14; exact fallback covers the rest */
#define WARPS   8
#define TPB     256

#define INFKEY ((0x7f800000ULL << 32) | 0x7fffffffULL)

// ---------------- scratch (device globals; no allocation allowed) ----------
__device__ unsigned long long g_cand[4096 * SEGS * KSEL];
__device__ int                g_ovf [4096 * SEGS];
__device__ float g_part_focal[4096];   // per-TILE partials (tile-keyed => deterministic)
__device__ float g_part_bbox [4096];
__device__ float g_part_giou [4096];
__device__ float g_part_delta[4096];
__device__ int   g_tile  = 0;          // focal work-steal counter
__device__ int   g_fdone = 0;          // filter-completion counter
__device__ int   g_ctr   = 0;          // finalize ticket

// ---------------- packed f32x2 helpers --------------------------------------
__device__ __forceinline__ unsigned long long pk2(float lo, float hi) {
    unsigned long long r;
    asm("mov.b64 %0, {%1, %2};" : "=l"(r) : "f"(lo), "f"(hi));
    return r;
}
__device__ __forceinline__ void upk2(unsigned long long v, float& lo, float& hi) {
    asm("mov.b64 {%0, %1}, %2;" : "=f"(lo), "=f"(hi) : "l"(v));
}
__device__ __forceinline__ unsigned long long fma2_(unsigned long long a,
                                                    unsigned long long b,
                                                    unsigned long long c) {
    unsigned long long d;
    asm("fma.rn.f32x2 %0, %1, %2, %3;" : "=l"(d) : "l"(a), "l"(b), "l"(c));
    return d;
}
__device__ __forceinline__ unsigned long long mul2_(unsigned long long a,
                                                    unsigned long long b) {
    unsigned long long d;
    asm("mul.rn.f32x2 %0, %1, %2;" : "=l"(d) : "l"(a), "l"(b));
    return d;
}
__device__ __forceinline__ unsigned long long add2_(unsigned long long a,
                                                    unsigned long long b) {
    unsigned long long d;
    asm("add.rn.f32x2 %0, %1, %2;" : "=l"(d) : "l"(a), "l"(b));
    return d;
}
__device__ __forceinline__ unsigned long long dup2(float c) {
    unsigned u = __float_as_uint(c);
    return ((unsigned long long)u << 32) | (unsigned long long)u;
}

// ---------------- focal pieces ---------------------------------------------
__device__ __forceinline__ float focal_t0(float x) {
    float ax   = fabsf(x);
    float u    = __expf(-ax);
    float r    = __fdividef(1.0f, 1.0f + u);
    float prob = (x >= 0.0f) ? r : (1.0f - r);
    float sp   = fmaxf(x, 0.0f) + __logf(1.0f + u);
    return 0.75f * sp * (prob * prob);
}
__device__ __forceinline__ float focal_t1(float x) {
    float ax   = fabsf(x);
    float u    = __expf(-ax);
    float r    = __fdividef(1.0f, 1.0f + u);
    float prob = (x >= 0.0f) ? r : (1.0f - r);
    float q    = 1.0f - prob;
    float spn  = fmaxf(-x, 0.0f) + __logf(1.0f + u);
    return 0.25f * spn * (q * q);
}

// 2-element focal_t0 core: 4 MUFU + packed-f32x2 minimax log1p (A&S 4.1.44,
// |eps| <= 3e-8 on [0,1]). Register-lean: ~12 live values.
__device__ __forceinline__ void fpair(float x0, float x1, unsigned long long& ACC) {
    float u0 = __expf(-fabsf(x0));
    float u1 = __expf(-fabsf(x1));
    float r0 = __fdividef(1.0f, 1.0f + u0);
    float r1 = __fdividef(1.0f, 1.0f + u1);
    unsigned long long U = pk2(u0, u1);
    unsigned long long t = fma2_(U, dup2(-0.0064535442f), dup2( 0.0360884937f));
    t = fma2_(t, U, dup2(-0.0953293897f));
    t = fma2_(t, U, dup2( 0.1676540711f));
    t = fma2_(t, U, dup2(-0.2407338084f));
    t = fma2_(t, U, dup2( 0.3317990258f));
    t = fma2_(t, U, dup2(-0.4998741238f));
    t = fma2_(t, U, dup2( 0.9999964239f));
    unsigned long long LG = mul2_(t, U);                 // log1p(u)
    unsigned long long SP = add2_(pk2(fmaxf(x0, 0.0f), fmaxf(x1, 0.0f)), LG);
    float p0 = (x0 >= 0.0f) ? r0 : (1.0f - r0);
    float p1 = (x1 >= 0.0f) ? r1 : (1.0f - r1);
    unsigned long long PR = pk2(p0, p1);
    ACC = fma2_(SP, mul2_(PR, PR), ACC);
}
__device__ __forceinline__ void focal4(float4 f, unsigned long long& ACC) {
    fpair(f.x, f.y, ACC);
    fpair(f.z, f.w, ACC);
}

// ---------------- top-9 helpers ---------------------------------------------
__device__ __forceinline__ void insert9(float (&dk)[KSEL], int (&ik)[KSEL],
                                        float d, int idx) {
    if (d < dk[KSEL - 1]) {
        dk[KSEL - 1] = d; ik[KSEL - 1] = idx;
#pragma unroll
        for (int j = KSEL - 1; j > 0; --j) {
            if (dk[j] < dk[j - 1]) {
                float td = dk[j]; dk[j] = dk[j - 1]; dk[j - 1] = td;
                int   ti = ik[j]; ik[j] = ik[j - 1]; ik[j - 1] = ti;
            }
        }
    }
}

__device__ __forceinline__ unsigned long long
warp_merge9(float (&dk)[KSEL], int (&ik)[KSEL], int lane) {
    unsigned long long mykey = INFKEY;
    unsigned long long key =
        (((unsigned long long)__float_as_uint(dk[0])) << 32) | (unsigned)ik[0];
#pragma unroll
    for (int r = 0; r < KSEL; ++r) {
        unsigned long long k = key;
#pragma unroll
        for (int off = 16; off > 0; off >>= 1) {
            unsigned long long o = __shfl_xor_sync(FULLMASK, k, off);
            k = (o < k) ? o : k;
        }
        if (lane == r) mykey = k;
        if (key == k) {
#pragma unroll
            for (int j = 0; j < KSEL - 1; ++j) { dk[j] = dk[j + 1]; ik[j] = ik[j + 1]; }
            dk[KSEL - 1] = __int_as_float(0x7f800000);
            ik[KSEL - 1] = 0x7fffffff;
            key = (((unsigned long long)__float_as_uint(dk[0])) << 32) | (unsigned)ik[0];
        }
    }
    return mykey;
}

// ---------------- THE kernel: filter -> merge -> focal steal -> finalize ----
__global__ void __launch_bounds__(TPB, 6)
mega_kernel(const float*  __restrict__ logits,
            const float4* __restrict__ pred_boxes,
            const float2* __restrict__ locs,
            const float4* __restrict__ gt_boxes,
            const int*    __restrict__ gt_labels,
            float* __restrict__ out,
            int B, int N, int C, int G, int FB, int MB,
            int n8f, int total, int NT, int tileUnits,
            double invBNC, double invBB, double invGI)
{
    __shared__ __align__(16) union {
        struct {
            float2 sloc[CHUNK];               // 14336 B
            int    sstk[WARPS][CAP][32];      // 16384 B (idx-only)
        } f;
        float  red[32];
        double dred[3][TPB];
    } sm;
    __shared__ int stile;
    __shared__ int sticket;

    const int tid  = threadIdx.x;
    const int lane = tid & 31;
    const int warp = tid >> 5;
    const int bid  = blockIdx.x;
    const int P    = B * G;

    // ================= role 1 (bids < FB): segment filter =====================
    if (bid < FB) {
        const int seg  = bid % SEGS;
        const int pair = (bid / SEGS) * WARPS + warp;
        const bool active = pair < P;

        float cx = 0.0f, cy = 0.0f;
        if (active) { float4 gb = gt_boxes[pair]; cx = gb.x; cy = gb.y; }

        const int segLen = (N + SEGS - 1) / SEGS;
        const int s0 = seg * segLen;
        const int s1 = min(N, s0 + segLen);

        int cnt = 0;
        for (int base = s0; base < s1; base += CHUNK) {
            int c = min(CHUNK, s1 - base);
            __syncthreads();
            for (int i = tid; i < c; i += TPB) sm.f.sloc[i] = locs[base + i];
            __syncthreads();
            if (active) {
                const float4* sl4 = (const float4*)sm.f.sloc;
                int c2 = c >> 1;
                for (int j = lane; j < c2; j += 32) {
                    float4 v  = sl4[j];
                    float dx0 = cx - v.x, dy0 = cy - v.y;
                    float dx1 = cx - v.z, dy1 = cy - v.w;
                    float d0  = fmaf(dx0, dx0, dy0 * dy0);
                    float d1  = fmaf(dx1, dx1, dy1 * dy1);
                    int   i0  = base + 2 * j;
                    if (d0 <= GATE2) {
                        if (cnt < CAP) sm.f.sstk[warp][cnt][lane] = i0;
                        cnt++;
                    }
                    if (d1 <= GATE2) {
                        if (cnt < CAP) sm.f.sstk[warp][cnt][lane] = i0 + 1;
                        cnt++;
                    }
                }
                if ((c & 1) != 0) {
                    int i = base + c - 1;
                    if (lane == (i & 31)) {
                        float2 L = sm.f.sloc[c - 1];
                        float dx = cx - L.x, dy = cy - L.y;
                        float d  = fmaf(dx, dx, dy * dy);
                        if (d <= GATE2) {
                            if (cnt < CAP) sm.f.sstk[warp][cnt][lane] = i;
                            cnt++;
                        }
                    }
                }
            }
        }
        if (active) {
            float dk[KSEL]; int ik[KSEL];
#pragma unroll
            for (int j = 0; j < KSEL; ++j) { dk[j] = __int_as_float(0x7f800000); ik[j] = 0x7fffffff; }
            int m = min(cnt, CAP);
            for (int i = 0; i < m; ++i) {
                int idx = sm.f.sstk[warp][i][lane];
                float2 L = locs[idx];                      // L2-hot recompute
                float dx = cx - L.x, dy = cy - L.y;
                insert9(dk, ik, fmaf(dx, dx, dy * dy), idx);
            }
            unsigned long long mykey = warp_merge9(dk, ik, lane);
            if (lane < KSEL) g_cand[(pair * SEGS + seg) * KSEL + lane] = mykey;
            int ovf = __ballot_sync(FULLMASK, cnt > CAP);
            if (lane == 0) g_ovf[pair * SEGS + seg] = (ovf != 0);
        }
        __syncthreads();            // all warps' results written
        __threadfence();
        if (tid == 0) atomicAdd(&g_fdone, 1);
        // fall through
    }

    // ================= role 2 (bids < MB): merge + box losses =================
    // Runs BEFORE the steal phase so it overlaps focal instead of trailing it.
    if (bid < MB) {
        if (tid == 0) {             // short spin: waits only for filter skew
            while (atomicAdd(&g_fdone, 0) < FB) __nanosleep(64);
        }
        __syncthreads();
        __threadfence();

        const int pair = bid * WARPS + warp;
        if (pair < P) {
            unsigned long long k0 = INFKEY, k1 = INFKEY;
            if (lane      < SEGS * KSEL) k0 = g_cand[pair * SEGS * KSEL + lane];
            if (lane + 32 < SEGS * KSEL) k1 = g_cand[pair * SEGS * KSEL + lane + 32];
            if (k1 < k0) { unsigned long long t = k0; k0 = k1; k1 = t; }

            unsigned long long mykey = INFKEY;
#pragma unroll
            for (int r = 0; r < KSEL; ++r) {
                unsigned long long k = k0;
#pragma unroll
                for (int off = 16; off > 0; off >>= 1) {
                    unsigned long long o = __shfl_xor_sync(FULLMASK, k, off);
                    k = (o < k) ? o : k;
                }
                if (lane == r) mykey = k;
                if (k0 == k) { k0 = k1; k1 = INFKEY; }
            }

            int ovf = 0;
            for (int s = 0; s < SEGS; ++s) ovf |= g_ovf[pair * SEGS + s];
            bool bad = (lane < KSEL) && ((unsigned)(mykey >> 32) >= 0x7f800000u);
            float4 gb = gt_boxes[pair];
            if (ovf || __ballot_sync(FULLMASK, bad)) {   // exact fallback (rare)
                float dk[KSEL]; int ik[KSEL];
#pragma unroll
                for (int j = 0; j < KSEL; ++j) { dk[j] = __int_as_float(0x7f800000); ik[j] = 0x7fffffff; }
                for (int n = lane; n < N; n += 32) {
                    float2 L = locs[n];
                    float dx = gb.x - L.x, dy = gb.y - L.y;
                    insert9(dk, ik, fmaf(dx, dx, dy * dy), n);
                }
                mykey = warp_merge9(dk, ik, lane);
            }

            const int b = pair / G;
            float l1 = 0.0f, gl = 0.0f, delta = 0.0f;
            if (lane < KSEL) {
                int myN = (int)(mykey & 0xffffffffULL);
                float4 pb = pred_boxes[(long long)b * N + myN];
                l1 = fabsf(pb.x - gb.x) + fabsf(pb.y - gb.y)
                   + fabsf(pb.z - gb.z) + fabsf(pb.w - gb.w);

                float ax0 = pb.x - 0.5f * pb.z, ay0 = pb.y - 0.5f * pb.w;
                float ax1 = pb.x + 0.5f * pb.z, ay1 = pb.y + 0.5f * pb.w;
                float bx0 = gb.x - 0.5f * gb.z, by0 = gb.y - 0.5f * gb.w;
                float bx1 = gb.x + 0.5f * gb.z, by1 = gb.y + 0.5f * gb.w;

                float area_a = (ax1 - ax0) * (ay1 - ay0);
                float area_b = (bx1 - bx0) * (by1 - by0);
                float iw = fmaxf(fminf(ax1, bx1) - fmaxf(ax0, bx0), 0.0f);
                float ih = fmaxf(fminf(ay1, by1) - fmaxf(ay0, by0), 0.0f);
                float inter = iw * ih;
                float uni   = area_a + area_b - inter;
                float iou   = inter / uni;
                float cw = fmaxf(fmaxf(ax1, bx1) - fminf(ax0, bx0), 0.0f);
                float ch = fmaxf(fmaxf(ay1, by1) - fminf(ay0, by0), 0.0f);
                float areac = cw * ch;
                gl = 1.0f - (iou - (areac - uni) / areac);

                int lbl = gt_labels[pair];
                float x = logits[(long long)(b * N + myN) * C + lbl];
                delta = focal_t1(x) - focal_t0(x);
            }
#pragma unroll
            for (int off = 16; off > 0; off >>= 1) {
                l1    += __shfl_down_sync(FULLMASK, l1,    off);
                gl    += __shfl_down_sync(FULLMASK, gl,    off);
                delta += __shfl_down_sync(FULLMASK, delta, off);
            }
            if (lane == 0) {
                g_part_bbox [pair] = l1;
                g_part_giou [pair] = gl;
                g_part_delta[pair] = delta;
            }
        }
    }

    // ================= role 3 (ALL blocks): focal tile stealing ===============
    {
        const float4* __restrict__ l4 = (const float4*)logits;
        const int itersPerTile = tileUnits / TPB;
        const float4 Z = make_float4(0.f, 0.f, 0.f, 0.f);
        for (;;) {
            __syncthreads();        // protects sm union + stile reuse
            if (tid == 0) stile = atomicAdd(&g_tile, 1);
            __syncthreads();
            const int t = stile;
            if (t >= NT) break;

            const int base = t * tileUnits;
            unsigned long long ACC = 0ULL;    // packed (0.0f, 0.0f)

            int  u = base + tid;
            bool v = (u < n8f);
            float4 a = v ? l4[2 * u]     : Z;
            float4 b = v ? l4[2 * u + 1] : Z;
            for (int k = 1; k < itersPerTile; ++k) {
                int  un = u + TPB;
                bool vn = (un < n8f);
                float4 an = vn ? l4[2 * un]     : Z;   // prefetch next
                float4 bn = vn ? l4[2 * un + 1] : Z;
                if (v) { focal4(a, ACC); focal4(b, ACC); }
                u = un; v = vn; a = an; b = bn;
            }
            if (v) { focal4(a, ACC); focal4(b, ACC); }

            float lo, hi;
            upk2(ACC, lo, hi);
            float acc = 0.75f * (lo + hi);
            if (t == NT - 1 && tid == 0) {   // scalar tail (tile-keyed => deterministic)
                for (int i = n8f * 8; i < total; ++i) acc += focal_t0(logits[i]);
            }
#pragma unroll
            for (int off = 16; off > 0; off >>= 1)
                acc += __shfl_down_sync(FULLMASK, acc, off);
            if (lane == 0) sm.red[warp] = acc;
            __syncthreads();
            if (warp == 0) {
                float vv = (lane < WARPS) ? sm.red[lane] : 0.0f;
#pragma unroll
                for (int off = 4; off > 0; off >>= 1)
                    vv += __shfl_down_sync(FULLMASK, vv, off);
                if (lane == 0) g_part_focal[t] = vv;
            }
        }
    }

    // ================= role 4: last block finalizes ===========================
    __threadfence();
    __syncthreads();
    if (tid == 0) sticket = atomicAdd(&g_ctr, 1);
    __syncthreads();
    if (sticket == (int)gridDim.x - 1) {
        double a0 = 0.0, a1 = 0.0, a2 = 0.0;
        for (int i = tid; i < NT; i += TPB) a0 += (double)g_part_focal[i];
        const int P2 = P;
        for (int i = tid; i < P2; i += TPB) {
            a0 += (double)g_part_delta[i];
            a1 += (double)g_part_bbox [i];
            a2 += (double)g_part_giou [i];
        }
        sm.dred[0][tid] = a0; sm.dred[1][tid] = a1; sm.dred[2][tid] = a2;
        __syncthreads();
#pragma unroll
        for (int s = 128; s > 0; s >>= 1) {
            if (tid < s) {
                sm.dred[0][tid] += sm.dred[0][tid + s];
                sm.dred[1][tid] += sm.dred[1][tid + s];
                sm.dred[2][tid] += sm.dred[2][tid + s];
            }
            __syncthreads();
        }
        if (tid == 0) {
            out[0] = (float)(sm.dred[0][0] * invBNC);
            out[1] = (float)(sm.dred[1][0] * invBB);
            out[2] = (float)(sm.dred[2][0] * invGI);
            g_ctr   = 0;    // self-reset for next graph replay
            g_tile  = 0;
            g_fdone = 0;
        }
    }
}

// ---------------- launch ----------------------------------------------------
extern "C" void kernel_launch(void* const* d_in, const int* in_sizes, int n_in,
                              void* d_out, int out_size)
{
    const float* logits = (const float*)d_in[0];   // (B,N,C)
    const float* pboxes = (const float*)d_in[1];   // (B,N,4)
    const float* locs   = (const float*)d_in[2];   // (N,2)
    const float* gboxes = (const float*)d_in[3];   // (B,G,4)
    const int*   glabel = (const int*)  d_in[4];   // (B,G)

    const int N = in_sizes[2] / 2;
    const int B = in_sizes[1] / (4 * N);
    const int C = in_sizes[0] / (B * N);
    const int G = in_sizes[4] / B;
    const int P = B * G;

    const int total = in_sizes[0];
    const int n8f   = total / 8;

    // focal tiling (tile-keyed partials; NT must fit g_part_focal)
    int tileUnits = 2048;                      // 8 iterations of 256 threads
    int NT = (n8f + tileUnits - 1) / tileUnits;
    while (NT > 4096) { tileUnits *= 2; NT = (n8f + tileUnits - 1) / tileUnits; }

    const int MB = (P + WARPS - 1) / WARPS;    // 128 merge blocks
    const int FB = MB * SEGS;                  // 512 filter blocks
    int grid = 6 * 148;                        // 888: fully resident at 6 CTAs/SM
    if (grid < FB) grid = FB;
    if (grid < MB + 1) grid = MB + 1;

    double invBNC = 1.0 / ((double)B * (double)N * (double)C);
    double invBB  = 1.0 / ((double)P * (double)KSEL * 4.0);
    double invGI  = 1.0 / ((double)P * (double)KSEL);

    mega_kernel<<<grid, TPB>>>(logits, (const float4*)pboxes,
                               (const float2*)locs, (const float4*)gboxes,
                               glabel, (float*)d_out,
                               B, N, C, G, FB, MB,
                               n8f, total, NT, tileUnits,
                               invBNC, invBB, invGI);
}